// round 2
// baseline (speedup 1.0000x reference)
#include <cuda_runtime.h>
#include <cuda_bf16.h>
#include <cstddef>

// ConvSelfAttention: o = Wout @ (val @ softmax_j(q^T k)) * gamma + x
// x = v.reshape(8,256,4096); qkv = Wqkv @ x ; q,k,val = 64-row slices.
//
// Pipeline (all fp32, FFMA2 f32x2 microkernel):
//  K0: transpose weights (WqkvT, WoutT)
//  K1: qkv GEMM  (192x4096x256 per batch)
//  K2: E = exp(q^T k) + row sums (store 1/L)  [no max-sub needed: |s| small]
//  K2.5: valT[i][d] = val[d][i] / L[i]
//  K3: y = valT^T @ E (split-K=2 partials)
//  K4: o = gamma * Wout @ y + x

#define NTOK 4096
#define NB 8

__device__ __align__(16) float g_WT[256 * 192];            // WqkvT [c][o]
__device__ __align__(16) float g_WoutT[64 * 256];          // [d][o]
__device__ __align__(16) float g_qkv[NB * 192 * NTOK];     // [b][o][n]
__device__ __align__(16) float g_E[(size_t)NB * NTOK * NTOK]; // exp(s) [b][i][j]
__device__ __align__(16) float g_linv[NB * NTOK];          // 1/rowsum
__device__ __align__(16) float g_valT[NB * NTOK * 64];     // val'/L, [b][i][d]
__device__ __align__(16) float g_yp[(size_t)2 * NB * 64 * NTOK]; // split-k partials

// ---------- packed f32x2 helpers ----------
__device__ __forceinline__ unsigned long long ffma2(unsigned long long a,
                                                    unsigned long long b,
                                                    unsigned long long c) {
    unsigned long long d;
    asm("fma.rn.f32x2 %0, %1, %2, %3;" : "=l"(d) : "l"(a), "l"(b), "l"(c));
    return d;
}
__device__ __forceinline__ unsigned long long dup2(float x) {
    unsigned long long d;
    asm("mov.b64 %0, {%1, %1};" : "=l"(d) : "r"(__float_as_uint(x)));
    return d;
}
__device__ __forceinline__ float2 unp2(unsigned long long v) {
    float2 r;
    asm("mov.b64 {%0, %1}, %2;" : "=f"(r.x), "=f"(r.y) : "l"(v));
    return r;
}

// ---------- 32-deep microkernel: C[64x128] tile, thread = 4 rows x 8 cols ----------
// As: 32x64 row-major (k-major), Bs: 32x128 row-major.
// acc[m][c] is a packed f32x2 pair of adjacent j columns.
__device__ __forceinline__ void gemm32(const float* __restrict__ As,
                                       const float* __restrict__ Bs,
                                       int ty, int tx,
                                       unsigned long long (&acc)[4][4]) {
#pragma unroll
    for (int kk = 0; kk < 32; kk++) {
        float4 a4 = *(const float4*)(As + kk * 64 + ty * 4);
        const ulonglong2* bp = (const ulonglong2*)(Bs + kk * 128 + tx * 8);
        ulonglong2 bA = bp[0];
        ulonglong2 bB = bp[1];
        unsigned long long a0 = dup2(a4.x), a1 = dup2(a4.y);
        unsigned long long a2 = dup2(a4.z), a3 = dup2(a4.w);
        acc[0][0] = ffma2(a0, bA.x, acc[0][0]); acc[0][1] = ffma2(a0, bA.y, acc[0][1]);
        acc[0][2] = ffma2(a0, bB.x, acc[0][2]); acc[0][3] = ffma2(a0, bB.y, acc[0][3]);
        acc[1][0] = ffma2(a1, bA.x, acc[1][0]); acc[1][1] = ffma2(a1, bA.y, acc[1][1]);
        acc[1][2] = ffma2(a1, bB.x, acc[1][2]); acc[1][3] = ffma2(a1, bB.y, acc[1][3]);
        acc[2][0] = ffma2(a2, bA.x, acc[2][0]); acc[2][1] = ffma2(a2, bA.y, acc[2][1]);
        acc[2][2] = ffma2(a2, bB.x, acc[2][2]); acc[2][3] = ffma2(a2, bB.y, acc[2][3]);
        acc[3][0] = ffma2(a3, bA.x, acc[3][0]); acc[3][1] = ffma2(a3, bA.y, acc[3][1]);
        acc[3][2] = ffma2(a3, bB.x, acc[3][2]); acc[3][3] = ffma2(a3, bB.y, acc[3][3]);
    }
}

__device__ __forceinline__ void acc_zero(unsigned long long (&acc)[4][4]) {
#pragma unroll
    for (int m = 0; m < 4; m++)
#pragma unroll
        for (int c = 0; c < 4; c++) acc[m][c] = 0ull;
}

// ---------- K0: weight transposes ----------
__global__ void k_wtrans(const float* __restrict__ Wqkv, const float* __restrict__ Wout) {
    int t = threadIdx.x;
    for (int i = t; i < 192 * 256; i += 256) {
        int o = i / 256, c = i % 256;
        g_WT[c * 192 + o] = Wqkv[i];
    }
    for (int i = t; i < 256 * 64; i += 256) {
        int o = i / 64, d = i % 64;
        g_WoutT[d * 256 + o] = Wout[i];
    }
}

// ---------- K1: qkv = Wqkv @ x ----------
__global__ void __launch_bounds__(256) k_qkv(const float* __restrict__ x) {
    __shared__ __align__(16) float A_s[32][64];
    __shared__ __align__(16) float B_s[32][128];
    int b = blockIdx.z, m0 = blockIdx.y * 64, n0 = blockIdx.x * 128;
    int tid = threadIdx.x, tx = tid & 15, ty = tid >> 4;
    unsigned long long acc[4][4];
    acc_zero(acc);
    for (int k0 = 0; k0 < 256; k0 += 32) {
        __syncthreads();
        for (int idx = tid; idx < 32 * 16; idx += 256) {
            int kk = idx >> 4, m4 = idx & 15;
            *(float4*)&A_s[kk][m4 * 4] =
                *(const float4*)&g_WT[(k0 + kk) * 192 + m0 + m4 * 4];
        }
        for (int idx = tid; idx < 32 * 32; idx += 256) {
            int kk = idx >> 5, n4 = idx & 31;
            *(float4*)&B_s[kk][n4 * 4] =
                *(const float4*)&x[(size_t)(b * 256 + k0 + kk) * NTOK + n0 + n4 * 4];
        }
        __syncthreads();
        gemm32(&A_s[0][0], &B_s[0][0], ty, tx, acc);
    }
#pragma unroll
    for (int m = 0; m < 4; m++) {
        float2 p0 = unp2(acc[m][0]), p1 = unp2(acc[m][1]);
        float2 p2 = unp2(acc[m][2]), p3 = unp2(acc[m][3]);
        float* dst = &g_qkv[(size_t)(b * 192 + m0 + ty * 4 + m) * NTOK + n0 + tx * 8];
        *(float4*)dst = make_float4(p0.x, p0.y, p1.x, p1.y);
        *(float4*)(dst + 4) = make_float4(p2.x, p2.y, p3.x, p3.y);
    }
}

// ---------- K2: E = exp(q^T k), rowsum -> 1/L ----------
__global__ void __launch_bounds__(256) k_scores() {
    __shared__ __align__(16) float Q_s[64][64];
    __shared__ __align__(16) float K_s[64][128];
    int b = blockIdx.y, i0 = blockIdx.x * 64;
    int tid = threadIdx.x, tx = tid & 15, ty = tid >> 4;

    for (int idx = tid; idx < 64 * 16; idx += 256) {
        int d = idx >> 4, i4 = idx & 15;
        *(float4*)&Q_s[d][i4 * 4] =
            *(const float4*)&g_qkv[(size_t)(b * 192 + d) * NTOK + i0 + i4 * 4];
    }
    float rsum[4] = {0.f, 0.f, 0.f, 0.f};

    for (int jt = 0; jt < 32; jt++) {
        int j0 = jt * 128;
        __syncthreads();
        for (int idx = tid; idx < 64 * 32; idx += 256) {
            int d = idx >> 5, n4 = idx & 31;
            *(float4*)&K_s[d][n4 * 4] =
                *(const float4*)&g_qkv[(size_t)(b * 192 + 64 + d) * NTOK + j0 + n4 * 4];
        }
        __syncthreads();
        unsigned long long acc[4][4];
        acc_zero(acc);
        gemm32(&Q_s[0][0], &K_s[0][0], ty, tx, acc);
        gemm32(&Q_s[32][0], &K_s[32][0], ty, tx, acc);
#pragma unroll
        for (int m = 0; m < 4; m++) {
            float2 p0 = unp2(acc[m][0]), p1 = unp2(acc[m][1]);
            float2 p2 = unp2(acc[m][2]), p3 = unp2(acc[m][3]);
            float e[8] = {p0.x, p0.y, p1.x, p1.y, p2.x, p2.y, p3.x, p3.y};
            float s = 0.f;
#pragma unroll
            for (int jj = 0; jj < 8; jj++) {
                e[jj] = __expf(e[jj]);   // |s| small by construction: no max-sub needed
                s += e[jj];
            }
            rsum[m] += s;
            size_t off = ((size_t)b * NTOK + i0 + ty * 4 + m) * NTOK + j0 + tx * 8;
            *(float4*)&g_E[off] = make_float4(e[0], e[1], e[2], e[3]);
            *(float4*)&g_E[off + 4] = make_float4(e[4], e[5], e[6], e[7]);
        }
    }
    // reduce rowsums across the 16 tx lanes (xor stays inside each half-warp)
#pragma unroll
    for (int m = 0; m < 4; m++) {
        float s = rsum[m];
        s += __shfl_xor_sync(0xffffffffu, s, 1);
        s += __shfl_xor_sync(0xffffffffu, s, 2);
        s += __shfl_xor_sync(0xffffffffu, s, 4);
        s += __shfl_xor_sync(0xffffffffu, s, 8);
        if (tx == 0) g_linv[b * NTOK + i0 + ty * 4 + m] = 1.0f / s;
    }
}

// ---------- K2.5: valT[i][d] = val[d][i] * (1/L[i]) ----------
__global__ void __launch_bounds__(256) k_valT() {
    __shared__ float V_s[64][65];
    int b = blockIdx.y, i0 = blockIdx.x * 64;
    int tid = threadIdx.x;
    for (int idx = tid; idx < 64 * 16; idx += 256) {
        int d = idx >> 4, i4 = idx & 15;
        float4 v4 = *(const float4*)&g_qkv[(size_t)(b * 192 + 128 + d) * NTOK + i0 + i4 * 4];
        V_s[d][i4 * 4 + 0] = v4.x;
        V_s[d][i4 * 4 + 1] = v4.y;
        V_s[d][i4 * 4 + 2] = v4.z;
        V_s[d][i4 * 4 + 3] = v4.w;
    }
    __syncthreads();
    for (int idx = tid; idx < 64 * 16; idx += 256) {
        int i = idx >> 4, p = idx & 15;
        float li = g_linv[b * NTOK + i0 + i];
        float4 o;
        o.x = V_s[p * 4 + 0][i] * li;
        o.y = V_s[p * 4 + 1][i] * li;
        o.z = V_s[p * 4 + 2][i] * li;
        o.w = V_s[p * 4 + 3][i] * li;
        *(float4*)&g_valT[(size_t)(b * NTOK + i0 + i) * 64 + p * 4] = o;
    }
}

// ---------- K3: y = valT^T @ E (split-K = 2) ----------
__global__ void __launch_bounds__(256) k_y() {
    __shared__ __align__(16) float A_s[32][64];
    __shared__ __align__(16) float B_s[32][128];
    int j0 = blockIdx.x * 128, b = blockIdx.y, ks = blockIdx.z;
    int tid = threadIdx.x, tx = tid & 15, ty = tid >> 4;
    unsigned long long acc[4][4];
    acc_zero(acc);
    for (int c = 0; c < 64; c++) {
        int i0 = ks * 2048 + c * 32;
        __syncthreads();
        for (int idx = tid; idx < 32 * 16; idx += 256) {
            int kk = idx >> 4, p = idx & 15;
            *(float4*)&A_s[kk][p * 4] =
                *(const float4*)&g_valT[(size_t)(b * NTOK + i0 + kk) * 64 + p * 4];
        }
        for (int idx = tid; idx < 32 * 32; idx += 256) {
            int kk = idx >> 5, p = idx & 31;
            *(float4*)&B_s[kk][p * 4] =
                *(const float4*)&g_E[((size_t)b * NTOK + i0 + kk) * NTOK + j0 + p * 4];
        }
        __syncthreads();
        gemm32(&A_s[0][0], &B_s[0][0], ty, tx, acc);
    }
#pragma unroll
    for (int m = 0; m < 4; m++) {
        float2 p0 = unp2(acc[m][0]), p1 = unp2(acc[m][1]);
        float2 p2 = unp2(acc[m][2]), p3 = unp2(acc[m][3]);
        float* dst = &g_yp[((size_t)(ks * NB + b) * 64 + ty * 4 + m) * NTOK + j0 + tx * 8];
        *(float4*)dst = make_float4(p0.x, p0.y, p1.x, p1.y);
        *(float4*)(dst + 4) = make_float4(p2.x, p2.y, p3.x, p3.y);
    }
}

// ---------- K4: o = gamma * Wout @ y + x ----------
__global__ void __launch_bounds__(256) k_out(const float* __restrict__ x,
                                             const float* __restrict__ gamma,
                                             float* __restrict__ out) {
    __shared__ __align__(16) float A_s[64][64];
    __shared__ __align__(16) float B_s[64][128];
    int j0 = blockIdx.x * 128, m0 = blockIdx.y * 64, b = blockIdx.z;
    int tid = threadIdx.x, tx = tid & 15, ty = tid >> 4;
    for (int idx = tid; idx < 64 * 16; idx += 256) {
        int d = idx >> 4, p = idx & 15;
        *(float4*)&A_s[d][p * 4] = *(const float4*)&g_WoutT[d * 256 + m0 + p * 4];
    }
    const size_t ypstride = (size_t)NB * 64 * NTOK;
    for (int idx = tid; idx < 64 * 32; idx += 256) {
        int d = idx >> 5, p = idx & 31;
        size_t off = ((size_t)(b * 64 + d)) * NTOK + j0 + p * 4;
        float4 y0 = *(const float4*)&g_yp[off];
        float4 y1 = *(const float4*)&g_yp[off + ypstride];
        B_s[d][p * 4 + 0] = y0.x + y1.x;
        B_s[d][p * 4 + 1] = y0.y + y1.y;
        B_s[d][p * 4 + 2] = y0.z + y1.z;
        B_s[d][p * 4 + 3] = y0.w + y1.w;
    }
    __syncthreads();
    unsigned long long acc[4][4];
    acc_zero(acc);
    gemm32(&A_s[0][0], &B_s[0][0], ty, tx, acc);
    gemm32(&A_s[32][0], &B_s[32][0], ty, tx, acc);
    float gm = gamma[0];
#pragma unroll
    for (int m = 0; m < 4; m++) {
        float2 p0 = unp2(acc[m][0]), p1 = unp2(acc[m][1]);
        float2 p2 = unp2(acc[m][2]), p3 = unp2(acc[m][3]);
        size_t off = (size_t)(b * 256 + m0 + ty * 4 + m) * NTOK + j0 + tx * 8;
        float4 x0 = *(const float4*)&x[off];
        float4 x1 = *(const float4*)&x[off + 4];
        *(float4*)&out[off] =
            make_float4(gm * p0.x + x0.x, gm * p0.y + x0.y, gm * p1.x + x0.z, gm * p1.y + x0.w);
        *(float4*)&out[off + 4] =
            make_float4(gm * p2.x + x1.x, gm * p2.y + x1.y, gm * p3.x + x1.z, gm * p3.y + x1.w);
    }
}

extern "C" void kernel_launch(void* const* d_in, const int* in_sizes, int n_in,
                              void* d_out, int out_size) {
    const float* v = (const float*)d_in[0];
    const float* Wqkv = (const float*)d_in[1];
    const float* Wout = (const float*)d_in[2];
    const float* gamma = (const float*)d_in[3];
    float* out = (float*)d_out;

    k_wtrans<<<1, 256>>>(Wqkv, Wout);

    dim3 g1(32, 3, NB);
    k_qkv<<<g1, 256>>>(v);

    dim3 g2(64, NB);
    k_scores<<<g2, 256>>>();

    dim3 g25(64, NB);
    k_valT<<<g25, 256>>>();

    dim3 g3(32, NB, 2);
    k_y<<<g3, 256>>>();

    dim3 g4(32, 4, NB);
    k_out<<<g4, 256>>>(v, gamma, out);
}

// round 8
// speedup vs baseline: 2.3823x; 2.3823x over previous
#include <cuda_runtime.h>
#include <cuda_bf16.h>
#include <cstdint>
#include <cstddef>

// ConvSelfAttention via legacy mma.sync (HMMA bf16, f32 accum) — the harness's
// ptxas target is plain sm_103 (no 'a'), so tcgen05 is unavailable.
//
//  k_prep : Wqkv,Wout -> bf16 ; zero rsum
//  k_xT   : x[b][c][n] -> xT[b][n][c] bf16
//  k_qkv  : qkvT[n][o] = xT @ Wqkv^T            (M=n, N=192, K=256)
//  k_sc   : E^T[j][i] = exp(k_j . q_i), rowsum(i) via atomics  (M=j, N=i, K=64)
//  k_vp   : val'[d][i] = vT[i][d] / L[i]
//  k_y    : yT[j][d] = E^T @ val'^T             (M=j, N=64, K=4096)
//  k_out  : out[o][j] = gamma * (yT @ Wout^T)^T[o][j] + x[o][j]  (M=j, N=64/CTA, K=64)

#define NTOK 4096
#define NB 8
#define LDT 72  // smem tile row pitch in bf16 elements (144B -> ldmatrix conflict-free)

typedef __nv_bfloat16 bf16;
typedef unsigned int u32;

__device__ bf16 g_Wq[192 * 256];                       // [o][c] K-major
__device__ bf16 g_Wo[256 * 64];                        // [o][d] K-major
__device__ bf16 g_xT[(size_t)NB * NTOK * 256];         // [b][n][c]
__device__ bf16 g_qkvT[(size_t)NB * NTOK * 192];       // [b][n][o]  (q|k|v slices)
__device__ bf16 g_vp[(size_t)NB * 64 * NTOK];          // val'/L  [b][d][i]
__device__ bf16 g_ET[(size_t)NB * NTOK * NTOK];        // exp(S)^T [b][j][i]
__device__ bf16 g_yT[(size_t)NB * NTOK * 64];          // [b][j][d]
__device__ float g_rsum[NB * NTOK];                    // softmax row sums (atomic)

extern __shared__ char dsm[];

// ---------------- helpers ----------------
__device__ __forceinline__ u32 s2u(const void* p) {
    u32 a;
    asm("{ .reg .u64 t; cvta.to.shared.u64 t, %1; cvt.u32.u64 %0, t; }" : "=r"(a) : "l"(p));
    return a;
}
__device__ __forceinline__ u32 pk_bf2(float lo, float hi) {  // {hi:lo} bf16x2
    u32 r;
    asm("cvt.rn.bf16x2.f32 %0, %1, %2;" : "=r"(r) : "f"(hi), "f"(lo));
    return r;
}
__device__ __forceinline__ void ldm4(u32* r, u32 addr) {
    asm volatile("ldmatrix.sync.aligned.m8n8.x4.shared.b16 {%0,%1,%2,%3}, [%4];"
                 : "=r"(r[0]), "=r"(r[1]), "=r"(r[2]), "=r"(r[3]) : "r"(addr));
}
__device__ __forceinline__ void mma16816(float* c, const u32* a, u32 b0, u32 b1) {
    asm volatile(
        "mma.sync.aligned.m16n8k16.row.col.f32.bf16.bf16.f32 "
        "{%0,%1,%2,%3}, {%4,%5,%6,%7}, {%8,%9}, {%0,%1,%2,%3};"
        : "+f"(c[0]), "+f"(c[1]), "+f"(c[2]), "+f"(c[3])
        : "r"(a[0]), "r"(a[1]), "r"(a[2]), "r"(a[3]), "r"(b0), "r"(b1));
}

// gmem (K-major rows of 64 bf16) -> smem tile with LDT pitch
__device__ __forceinline__ void load_tile(bf16* sm, const bf16* src, int rows, int stride) {
    for (int idx = threadIdx.x; idx < rows * 8; idx += blockDim.x) {
        int r = idx >> 3, c = idx & 7;
        *(uint4*)(sm + r * LDT + c * 8) = *(const uint4*)(src + (size_t)r * stride + c * 8);
    }
}

// Warp GEMM over one K=64 smem chunk. Warp tile: (MT*16) x (NTP*16).
// sA/sB are warp-adjusted smem byte addresses (K-major, pitch LDT).
template <int MT, int NTP>
__device__ __forceinline__ void wmma64(u32 sA, u32 sB, float (&acc)[MT][2 * NTP][4]) {
    const int l = threadIdx.x & 31;
    const u32 aoff = (u32)((((l & 15) * LDT) + (l >> 4) * 8) * 2);
    const u32 boff = (u32)(((((l & 7) + ((l >> 4) << 3)) * LDT) + ((l >> 3) & 1) * 8) * 2);
#pragma unroll
    for (int ks = 0; ks < 4; ks++) {
        u32 a[MT][4], b[NTP][4];
#pragma unroll
        for (int mt = 0; mt < MT; mt++)
            ldm4(a[mt], sA + aoff + (u32)((mt * 16 * LDT + ks * 16) * 2));
#pragma unroll
        for (int np = 0; np < NTP; np++)
            ldm4(b[np], sB + boff + (u32)((np * 16 * LDT + ks * 16) * 2));
#pragma unroll
        for (int mt = 0; mt < MT; mt++)
#pragma unroll
            for (int np = 0; np < NTP; np++) {
                mma16816(acc[mt][2 * np], a[mt], b[np][0], b[np][1]);
                mma16816(acc[mt][2 * np + 1], a[mt], b[np][2], b[np][3]);
            }
    }
}

// ---------------- k_prep ----------------
__global__ void k_prep(const float* __restrict__ Wqkv, const float* __restrict__ Wout) {
    int idx = blockIdx.x * 256 + threadIdx.x;
    if (idx < 192 * 256) {
        g_Wq[idx] = __float2bfloat16(Wqkv[idx]);
    } else if (idx < 192 * 256 + 256 * 64) {
        int j = idx - 192 * 256;
        g_Wo[j] = __float2bfloat16(Wout[j]);
    } else {
        int j = idx - (192 * 256 + 256 * 64);
        if (j < NB * NTOK) g_rsum[j] = 0.0f;
    }
}

// ---------------- k_xT: x[c][n] -> xT[n][c] bf16 ----------------
__global__ void __launch_bounds__(256) k_xT(const float* __restrict__ x) {
    __shared__ float sv[64][65];
    int b = blockIdx.z, c0 = blockIdx.y * 64, n0 = blockIdx.x * 64;
    for (int lin = threadIdx.x; lin < 4096; lin += 256) {
        int cl = lin >> 6, nl = lin & 63;
        sv[cl][nl] = x[((size_t)(b * 256 + c0 + cl)) * NTOK + n0 + nl];
    }
    __syncthreads();
    for (int lin = threadIdx.x; lin < 4096; lin += 256) {
        int nl = lin >> 6, cl = lin & 63;
        g_xT[((size_t)b * NTOK + n0 + nl) * 256 + c0 + cl] = __float2bfloat16(sv[cl][nl]);
    }
}

// ---------------- k_qkv: qkvT[n][o] = xT @ Wq^T ----------------
__global__ void __launch_bounds__(256) k_qkv() {
    bf16* At = (bf16*)dsm;                 // 128 x 64 (pitch 72) = 18432 B
    bf16* Bt = (bf16*)(dsm + 18432);       // 192 x 64            = 27648 B
    int b = blockIdx.y, n0 = blockIdx.x * 128;
    int tid = threadIdx.x, wid = tid >> 5, l = tid & 31;
    int wm = wid & 3, wn = wid >> 2;  // 4 m-warps x 2 n-warps; warp tile 32x96
    float acc[2][12][4];
#pragma unroll
    for (int mt = 0; mt < 2; mt++)
#pragma unroll
        for (int nt = 0; nt < 12; nt++)
#pragma unroll
            for (int e = 0; e < 4; e++) acc[mt][nt][e] = 0.f;

    const bf16* asrc = g_xT + ((size_t)b * NTOK + n0) * 256;
    for (int kc = 0; kc < 4; kc++) {
        __syncthreads();
        load_tile(At, asrc + kc * 64, 128, 256);
        load_tile(Bt, g_Wq + kc * 64, 192, 256);
        __syncthreads();
        wmma64<2, 6>(s2u(At) + (u32)(wm * 32 * LDT * 2),
                     s2u(Bt) + (u32)(wn * 96 * LDT * 2), acc);
    }
#pragma unroll
    for (int mt = 0; mt < 2; mt++)
#pragma unroll
        for (int nt = 0; nt < 12; nt++) {
            int j = n0 + wm * 32 + mt * 16 + (l >> 2);
            int o = wn * 96 + nt * 8 + (l & 3) * 2;
            *(u32*)(g_qkvT + ((size_t)b * NTOK + j) * 192 + o) =
                pk_bf2(acc[mt][nt][0], acc[mt][nt][1]);
            *(u32*)(g_qkvT + ((size_t)b * NTOK + j + 8) * 192 + o) =
                pk_bf2(acc[mt][nt][2], acc[mt][nt][3]);
        }
}

// ---------------- k_sc: E^T[j][i] = exp(k_j . q_i), rowsum -> g_rsum ----------------
__global__ void __launch_bounds__(256) k_sc() {
    bf16* At = (bf16*)dsm;                 // kT tile 128x64 = 18432 B
    bf16* Bt = (bf16*)(dsm + 18432);       // qT tile 128x64 = 18432 B
    int i0 = blockIdx.x * 128, j0 = blockIdx.y * 128, b = blockIdx.z;
    int tid = threadIdx.x, wid = tid >> 5, l = tid & 31;
    int wm = wid & 3, wn = wid >> 2;  // warp tile 32(j) x 64(i)
    load_tile(At, g_qkvT + ((size_t)b * NTOK + j0) * 192 + 64, 128, 192);
    load_tile(Bt, g_qkvT + ((size_t)b * NTOK + i0) * 192, 128, 192);
    __syncthreads();
    float acc[2][8][4];
#pragma unroll
    for (int mt = 0; mt < 2; mt++)
#pragma unroll
        for (int nt = 0; nt < 8; nt++)
#pragma unroll
            for (int e = 0; e < 4; e++) acc[mt][nt][e] = 0.f;
    wmma64<2, 4>(s2u(At) + (u32)(wm * 32 * LDT * 2),
                 s2u(Bt) + (u32)(wn * 64 * LDT * 2), acc);

    float cs[8][2];
#pragma unroll
    for (int nt = 0; nt < 8; nt++) cs[nt][0] = cs[nt][1] = 0.f;
    const size_t ebase = (size_t)b * NTOK * NTOK;
#pragma unroll
    for (int mt = 0; mt < 2; mt++)
#pragma unroll
        for (int nt = 0; nt < 8; nt++) {
            float e0 = __expf(acc[mt][nt][0]);
            float e1 = __expf(acc[mt][nt][1]);
            float e2 = __expf(acc[mt][nt][2]);
            float e3 = __expf(acc[mt][nt][3]);
            cs[nt][0] += e0 + e2;
            cs[nt][1] += e1 + e3;
            int j = j0 + wm * 32 + mt * 16 + (l >> 2);
            int i = i0 + wn * 64 + nt * 8 + (l & 3) * 2;
            *(u32*)(g_ET + ebase + (size_t)j * NTOK + i) = pk_bf2(e0, e1);
            *(u32*)(g_ET + ebase + (size_t)(j + 8) * NTOK + i) = pk_bf2(e2, e3);
        }
#pragma unroll
    for (int nt = 0; nt < 8; nt++) {
        float s0 = cs[nt][0], s1 = cs[nt][1];
#pragma unroll
        for (int d = 4; d < 32; d <<= 1) {
            s0 += __shfl_xor_sync(0xffffffffu, s0, d);
            s1 += __shfl_xor_sync(0xffffffffu, s1, d);
        }
        if (l < 4) {
            int i = i0 + wn * 64 + nt * 8 + l * 2;
            atomicAdd(&g_rsum[b * NTOK + i], s0);
            atomicAdd(&g_rsum[b * NTOK + i + 1], s1);
        }
    }
}

// ---------------- k_vp: val'[d][i] = vT[i][d] / L[i] ----------------
__global__ void __launch_bounds__(256) k_vp() {
    __shared__ float sv[64][65];
    int b = blockIdx.y, n0 = blockIdx.x * 64;
    for (int lin = threadIdx.x; lin < 4096; lin += 256) {
        int nl = lin >> 6, dl = lin & 63;
        sv[nl][dl] =
            __bfloat162float(g_qkvT[((size_t)b * NTOK + n0 + nl) * 192 + 128 + dl]);
    }
    __syncthreads();
    for (int lin = threadIdx.x; lin < 4096; lin += 256) {
        int nl = lin & 63, dl = lin >> 6;
        float li = 1.0f / g_rsum[b * NTOK + n0 + nl];
        g_vp[((size_t)(b * 64 + dl)) * NTOK + n0 + nl] = __float2bfloat16(sv[nl][dl] * li);
    }
}

// ---------------- k_y: yT[j][d] = E^T @ val'^T ----------------
__global__ void __launch_bounds__(128) k_y() {
    bf16* At = (bf16*)dsm;                 // E^T tile 128x64 = 18432 B
    bf16* Bt = (bf16*)(dsm + 18432);       // vp tile  64x64  =  9216 B
    int b = blockIdx.y, j0 = blockIdx.x * 128;
    int tid = threadIdx.x, wid = tid >> 5, l = tid & 31;  // 4 j-warps, tile 32x64
    float acc[2][8][4];
#pragma unroll
    for (int mt = 0; mt < 2; mt++)
#pragma unroll
        for (int nt = 0; nt < 8; nt++)
#pragma unroll
            for (int e = 0; e < 4; e++) acc[mt][nt][e] = 0.f;

    const bf16* asrc = g_ET + (size_t)b * NTOK * NTOK + (size_t)j0 * NTOK;
    const bf16* bsrc = g_vp + (size_t)b * 64 * NTOK;
    for (int ic = 0; ic < 64; ic++) {
        __syncthreads();
        load_tile(At, asrc + ic * 64, 128, NTOK);
        load_tile(Bt, bsrc + ic * 64, 64, NTOK);
        __syncthreads();
        wmma64<2, 4>(s2u(At) + (u32)(wid * 32 * LDT * 2), s2u(Bt), acc);
    }
#pragma unroll
    for (int mt = 0; mt < 2; mt++)
#pragma unroll
        for (int nt = 0; nt < 8; nt++) {
            int j = j0 + wid * 32 + mt * 16 + (l >> 2);
            int d = nt * 8 + (l & 3) * 2;
            *(u32*)(g_yT + ((size_t)b * NTOK + j) * 64 + d) =
                pk_bf2(acc[mt][nt][0], acc[mt][nt][1]);
            *(u32*)(g_yT + ((size_t)b * NTOK + j + 8) * 64 + d) =
                pk_bf2(acc[mt][nt][2], acc[mt][nt][3]);
        }
}

// ---------------- k_out: out[o][j] = gm * (yT @ Wo^T)^T + x ----------------
__global__ void __launch_bounds__(128) k_out(const float* __restrict__ x,
                                             const float* __restrict__ gamma,
                                             float* __restrict__ out) {
    bf16* At = (bf16*)dsm;                 // yT tile 128x64 = 18432 B
    bf16* Bt = (bf16*)(dsm + 18432);       // Wo tile  64x64 =  9216 B
    float* Ts = (float*)dsm;               // reused: 64 x 132 f32 = 33792 B
    int j0 = blockIdx.x * 128, o0 = blockIdx.y * 64, b = blockIdx.z;
    int tid = threadIdx.x, wid = tid >> 5, l = tid & 31;  // 4 j-warps, tile 32x64
    load_tile(At, g_yT + ((size_t)b * NTOK + j0) * 64, 128, 64);
    load_tile(Bt, g_Wo + o0 * 64, 64, 64);
    __syncthreads();
    float acc[2][8][4];
#pragma unroll
    for (int mt = 0; mt < 2; mt++)
#pragma unroll
        for (int nt = 0; nt < 8; nt++)
#pragma unroll
            for (int e = 0; e < 4; e++) acc[mt][nt][e] = 0.f;
    wmma64<2, 4>(s2u(At) + (u32)(wid * 32 * LDT * 2), s2u(Bt), acc);
    __syncthreads();  // done reading tiles; reuse smem for transpose
#pragma unroll
    for (int mt = 0; mt < 2; mt++)
#pragma unroll
        for (int nt = 0; nt < 8; nt++) {
            int jl = wid * 32 + mt * 16 + (l >> 2);
            int ol = nt * 8 + (l & 3) * 2;
            Ts[ol * 132 + jl] = acc[mt][nt][0];
            Ts[(ol + 1) * 132 + jl] = acc[mt][nt][1];
            Ts[ol * 132 + jl + 8] = acc[mt][nt][2];
            Ts[(ol + 1) * 132 + jl + 8] = acc[mt][nt][3];
        }
    __syncthreads();
    float gm = gamma[0];
    int row = tid >> 1, half = (tid & 1) * 64;
    size_t goff = ((size_t)(b * 256 + o0 + row)) * NTOK + j0 + half;
#pragma unroll
    for (int q = 0; q < 16; q++) {
        float4 s = *(float4*)&Ts[row * 132 + half + q * 4];
        float4 xv = *(const float4*)&x[goff + q * 4];
        float4 o;
        o.x = fmaf(gm, s.x, xv.x);
        o.y = fmaf(gm, s.y, xv.y);
        o.z = fmaf(gm, s.z, xv.z);
        o.w = fmaf(gm, s.w, xv.w);
        *(float4*)&out[goff + q * 4] = o;
    }
}

extern "C" void kernel_launch(void* const* d_in, const int* in_sizes, int n_in,
                              void* d_out, int out_size) {
    const float* v = (const float*)d_in[0];
    const float* Wqkv = (const float*)d_in[1];
    const float* Wout = (const float*)d_in[2];
    const float* gamma = (const float*)d_in[3];
    float* out = (float*)d_out;

    k_prep<<<384, 256>>>(Wqkv, Wout);
    k_xT<<<dim3(64, 4, NB), 256>>>(v);
    k_qkv<<<dim3(32, NB), 256, 18432 + 27648>>>();
    k_sc<<<dim3(32, 32, NB), 256, 18432 + 18432>>>();
    k_vp<<<dim3(64, NB), 256>>>();
    k_y<<<dim3(32, NB), 128, 18432 + 9216>>>();
    k_out<<<dim3(32, 4, NB), 128, 33792>>>(v, gamma, out);
}

// round 9
// speedup vs baseline: 6.4486x; 2.7068x over previous
#include <cuda_runtime.h>
#include <cuda_bf16.h>
#include <cstdint>
#include <cstddef>

// ConvSelfAttention via mma.sync HMMA bf16 (ptxas target is plain sm_103 -> no tcgen05).
// Flash-style: exp(S) lives only in SMEM, never in DRAM.
//
//  k_prep : Wqkv,Wout -> bf16 ; zero rsum
//  k_xT   : x[b][c][n] -> xT[b][n][c] bf16
//  k_qkv  : qkvT[n][o] = xT @ Wqkv^T            (M=n, N=192, K=256)
//  k_lsum : L[i] = sum_j exp(q_i . k_j)   (Q-frags in regs, loop over k-tiles)
//  k_vp   : vp[d][i] = val[d][i] / L[i]
//  k_attn : yT[j][d] = sum_i exp(k_j.q_i) * vp[d][i]  (recompute E per tile in smem)
//  k_out  : out[o][j] = gamma * (yT @ Wout^T)^T[o][j] + x[o][j]

#define NTOK 4096
#define NB 8
#define LDT 72  // smem row pitch in bf16 (144B, 16B-aligned, ldmatrix conflict-free)

typedef __nv_bfloat16 bf16;
typedef unsigned int u32;

__device__ bf16 g_Wq[192 * 256];                 // [o][c] K-major
__device__ bf16 g_Wo[256 * 64];                  // [o][d] K-major
__device__ bf16 g_xT[(size_t)NB * NTOK * 256];   // [b][n][c]
__device__ bf16 g_qkvT[(size_t)NB * NTOK * 192]; // [b][n][o]  (q|k|v)
__device__ bf16 g_vp[(size_t)NB * 64 * NTOK];    // val/L  [b][d][i]
__device__ bf16 g_yT[(size_t)NB * NTOK * 64];    // [b][j][d]
__device__ float g_rsum[NB * NTOK];              // softmax row sums (atomic)

extern __shared__ char dsm[];

// ---------------- helpers ----------------
__device__ __forceinline__ u32 s2u(const void* p) {
    u32 a;
    asm("{ .reg .u64 t; cvta.to.shared.u64 t, %1; cvt.u32.u64 %0, t; }" : "=r"(a) : "l"(p));
    return a;
}
__device__ __forceinline__ u32 pk_bf2(float lo, float hi) {
    u32 r;
    asm("cvt.rn.bf16x2.f32 %0, %1, %2;" : "=r"(r) : "f"(hi), "f"(lo));
    return r;
}
__device__ __forceinline__ void ldm4(u32* r, u32 addr) {
    asm volatile("ldmatrix.sync.aligned.m8n8.x4.shared.b16 {%0,%1,%2,%3}, [%4];"
                 : "=r"(r[0]), "=r"(r[1]), "=r"(r[2]), "=r"(r[3]) : "r"(addr));
}
__device__ __forceinline__ void mma16816(float* c, const u32* a, u32 b0, u32 b1) {
    asm volatile(
        "mma.sync.aligned.m16n8k16.row.col.f32.bf16.bf16.f32 "
        "{%0,%1,%2,%3}, {%4,%5,%6,%7}, {%8,%9}, {%0,%1,%2,%3};"
        : "+f"(c[0]), "+f"(c[1]), "+f"(c[2]), "+f"(c[3])
        : "r"(a[0]), "r"(a[1]), "r"(a[2]), "r"(a[3]), "r"(b0), "r"(b1));
}
// lane sub-offsets for ldmatrix A (16x16 row-major) and B (16x16 col-major)
__device__ __forceinline__ u32 a_off(int l) {
    return (u32)((((l & 15) * LDT) + (l >> 4) * 8) * 2);
}
__device__ __forceinline__ u32 b_off(int l) {
    return (u32)(((((l & 7) + ((l >> 4) << 3)) * LDT) + ((l >> 3) & 1) * 8) * 2);
}

// gmem (K-major rows of 64 bf16) -> smem tile with LDT pitch
__device__ __forceinline__ void load_tile(bf16* sm, const bf16* src, int rows, int stride) {
    for (int idx = threadIdx.x; idx < rows * 8; idx += blockDim.x) {
        int r = idx >> 3, c = idx & 7;
        *(uint4*)(sm + r * LDT + c * 8) = *(const uint4*)(src + (size_t)r * stride + c * 8);
    }
}

// Warp GEMM over one K=64 smem chunk (A and B both from smem).
template <int MT, int NTP>
__device__ __forceinline__ void wmma64(u32 sA, u32 sB, float (&acc)[MT][2 * NTP][4]) {
    const int l = threadIdx.x & 31;
    const u32 aoff = a_off(l), boff = b_off(l);
#pragma unroll
    for (int ks = 0; ks < 4; ks++) {
        u32 a[MT][4], b[NTP][4];
#pragma unroll
        for (int mt = 0; mt < MT; mt++)
            ldm4(a[mt], sA + aoff + (u32)((mt * 16 * LDT + ks * 16) * 2));
#pragma unroll
        for (int np = 0; np < NTP; np++)
            ldm4(b[np], sB + boff + (u32)((np * 16 * LDT + ks * 16) * 2));
#pragma unroll
        for (int mt = 0; mt < MT; mt++)
#pragma unroll
            for (int np = 0; np < NTP; np++) {
                mma16816(acc[mt][2 * np], a[mt], b[np][0], b[np][1]);
                mma16816(acc[mt][2 * np + 1], a[mt], b[np][2], b[np][3]);
            }
    }
}

// ---------------- k_prep ----------------
__global__ void k_prep(const float* __restrict__ Wqkv, const float* __restrict__ Wout) {
    int idx = blockIdx.x * 256 + threadIdx.x;
    if (idx < 192 * 256) {
        g_Wq[idx] = __float2bfloat16(Wqkv[idx]);
    } else if (idx < 192 * 256 + 256 * 64) {
        int j = idx - 192 * 256;
        g_Wo[j] = __float2bfloat16(Wout[j]);
    } else {
        int j = idx - (192 * 256 + 256 * 64);
        if (j < NB * NTOK) g_rsum[j] = 0.0f;
    }
}

// ---------------- k_xT ----------------
__global__ void __launch_bounds__(256) k_xT(const float* __restrict__ x) {
    __shared__ float sv[64][65];
    int b = blockIdx.z, c0 = blockIdx.y * 64, n0 = blockIdx.x * 64;
    for (int lin = threadIdx.x; lin < 4096; lin += 256) {
        int cl = lin >> 6, nl = lin & 63;
        sv[cl][nl] = x[((size_t)(b * 256 + c0 + cl)) * NTOK + n0 + nl];
    }
    __syncthreads();
    for (int lin = threadIdx.x; lin < 4096; lin += 256) {
        int nl = lin >> 6, cl = lin & 63;
        g_xT[((size_t)b * NTOK + n0 + nl) * 256 + c0 + cl] = __float2bfloat16(sv[cl][nl]);
    }
}

// ---------------- k_qkv ----------------
__global__ void __launch_bounds__(256) k_qkv() {
    bf16* At = (bf16*)dsm;            // 128 x 64 (pitch 72) = 18432 B
    bf16* Bt = (bf16*)(dsm + 18432);  // 192 x 64            = 27648 B
    int b = blockIdx.y, n0 = blockIdx.x * 128;
    int tid = threadIdx.x, wid = tid >> 5, l = tid & 31;
    int wm = wid & 3, wn = wid >> 2;
    float acc[2][12][4];
#pragma unroll
    for (int mt = 0; mt < 2; mt++)
#pragma unroll
        for (int nt = 0; nt < 12; nt++)
#pragma unroll
            for (int e = 0; e < 4; e++) acc[mt][nt][e] = 0.f;

    const bf16* asrc = g_xT + ((size_t)b * NTOK + n0) * 256;
    for (int kc = 0; kc < 4; kc++) {
        __syncthreads();
        load_tile(At, asrc + kc * 64, 128, 256);
        load_tile(Bt, g_Wq + kc * 64, 192, 256);
        __syncthreads();
        wmma64<2, 6>(s2u(At) + (u32)(wm * 32 * LDT * 2),
                     s2u(Bt) + (u32)(wn * 96 * LDT * 2), acc);
    }
#pragma unroll
    for (int mt = 0; mt < 2; mt++)
#pragma unroll
        for (int nt = 0; nt < 12; nt++) {
            int j = n0 + wm * 32 + mt * 16 + (l >> 2);
            int o = wn * 96 + nt * 8 + (l & 3) * 2;
            *(u32*)(g_qkvT + ((size_t)b * NTOK + j) * 192 + o) =
                pk_bf2(acc[mt][nt][0], acc[mt][nt][1]);
            *(u32*)(g_qkvT + ((size_t)b * NTOK + j + 8) * 192 + o) =
                pk_bf2(acc[mt][nt][2], acc[mt][nt][3]);
        }
}

// ---------------- k_lsum: L[i] = sum_j exp(q_i . k_j) ----------------
__global__ void __launch_bounds__(256) k_lsum() {
    bf16* Bt = (bf16*)dsm;  // 128 x 72 = 18432 B (stages qT, then kT tiles)
    int b = blockIdx.y, i0 = blockIdx.x * 128;
    int tid = threadIdx.x, wid = tid >> 5, l = tid & 31;
    int wm = wid & 3, wn = wid >> 2;  // wm: i-warp (4x32), wn: j-half (2x64)

    // stage qT i-tile, capture A fragments in registers
    load_tile(Bt, g_qkvT + ((size_t)b * NTOK + i0) * 192, 128, 192);
    __syncthreads();
    u32 qA[2][4][4];
    {
        u32 base = s2u(Bt) + (u32)(wm * 32 * LDT * 2) + a_off(l);
#pragma unroll
        for (int mt = 0; mt < 2; mt++)
#pragma unroll
            for (int ks = 0; ks < 4; ks++)
                ldm4(qA[mt][ks], base + (u32)((mt * 16 * LDT + ks * 16) * 2));
    }
    float rs[2][2] = {{0.f, 0.f}, {0.f, 0.f}};
    const u32 boff = b_off(l);

    for (int jt = 0; jt < 32; jt++) {
        __syncthreads();
        load_tile(Bt, g_qkvT + ((size_t)b * NTOK + jt * 128) * 192 + 64, 128, 192);
        __syncthreads();
        float S[2][8][4];
#pragma unroll
        for (int mt = 0; mt < 2; mt++)
#pragma unroll
            for (int nt = 0; nt < 8; nt++)
#pragma unroll
                for (int e = 0; e < 4; e++) S[mt][nt][e] = 0.f;
        u32 bbase = s2u(Bt) + (u32)(wn * 64 * LDT * 2) + boff;
#pragma unroll
        for (int ks = 0; ks < 4; ks++) {
            u32 bf[4][4];
#pragma unroll
            for (int np = 0; np < 4; np++)
                ldm4(bf[np], bbase + (u32)((np * 16 * LDT + ks * 16) * 2));
#pragma unroll
            for (int mt = 0; mt < 2; mt++)
#pragma unroll
                for (int np = 0; np < 4; np++) {
                    mma16816(S[mt][2 * np], qA[mt][ks], bf[np][0], bf[np][1]);
                    mma16816(S[mt][2 * np + 1], qA[mt][ks], bf[np][2], bf[np][3]);
                }
        }
#pragma unroll
        for (int mt = 0; mt < 2; mt++)
#pragma unroll
            for (int nt = 0; nt < 8; nt++) {
                rs[mt][0] += __expf(S[mt][nt][0]) + __expf(S[mt][nt][1]);
                rs[mt][1] += __expf(S[mt][nt][2]) + __expf(S[mt][nt][3]);
            }
    }
    // reduce over the 4 lanes holding different j-columns of the same row
#pragma unroll
    for (int mt = 0; mt < 2; mt++)
#pragma unroll
        for (int h = 0; h < 2; h++) {
            float s = rs[mt][h];
            s += __shfl_xor_sync(0xffffffffu, s, 1);
            s += __shfl_xor_sync(0xffffffffu, s, 2);
            if ((l & 3) == 0)
                atomicAdd(&g_rsum[b * NTOK + i0 + wm * 32 + mt * 16 + (l >> 2) + h * 8], s);
        }
}

// ---------------- k_vp: vp[d][i] = val[d][i] / L[i] ----------------
__global__ void __launch_bounds__(256) k_vp() {
    __shared__ float sv[64][65];
    int b = blockIdx.y, n0 = blockIdx.x * 64;
    for (int lin = threadIdx.x; lin < 4096; lin += 256) {
        int nl = lin >> 6, dl = lin & 63;
        sv[nl][dl] =
            __bfloat162float(g_qkvT[((size_t)b * NTOK + n0 + nl) * 192 + 128 + dl]);
    }
    __syncthreads();
    for (int lin = threadIdx.x; lin < 4096; lin += 256) {
        int nl = lin & 63, dl = lin >> 6;
        float li = 1.0f / g_rsum[b * NTOK + n0 + nl];
        g_vp[((size_t)(b * 64 + dl)) * NTOK + n0 + nl] = __float2bfloat16(sv[nl][dl] * li);
    }
}

// ---------------- k_attn: yT[j][d] = sum_i exp(k_j.q_i) vp[d][i] ----------------
__global__ void __launch_bounds__(256) k_attn() {
    bf16* At = (bf16*)dsm;            // qT i-chunk  64 x 72 = 9216 B
    bf16* Bt = (bf16*)(dsm + 9216);   // vp chunk    64 x 72 = 9216 B
    bf16* Et = (bf16*)(dsm + 18432);  // E^T tile   128 x 72 = 18432 B (also stages kT)
    int b = blockIdx.y, j0 = blockIdx.x * 128;
    int tid = threadIdx.x, wid = tid >> 5, l = tid & 31;
    int wm = wid & 3, wn = wid >> 2;  // wm: j-warp (4x32); wn: i/d-half (2x32)

    // stage kT j-tile in Et region, capture A fragments in registers
    load_tile(Et, g_qkvT + ((size_t)b * NTOK + j0) * 192 + 64, 128, 192);
    __syncthreads();
    u32 kA[2][4][4];
    {
        u32 base = s2u(Et) + (u32)(wm * 32 * LDT * 2) + a_off(l);
#pragma unroll
        for (int mt = 0; mt < 2; mt++)
#pragma unroll
            for (int ks = 0; ks < 4; ks++)
                ldm4(kA[mt][ks], base + (u32)((mt * 16 * LDT + ks * 16) * 2));
    }
    float ya[2][4][4];
#pragma unroll
    for (int mt = 0; mt < 2; mt++)
#pragma unroll
        for (int nt = 0; nt < 4; nt++)
#pragma unroll
            for (int e = 0; e < 4; e++) ya[mt][nt][e] = 0.f;

    const u32 aoff = a_off(l), boff = b_off(l);
    const bf16* qsrc = g_qkvT + (size_t)b * NTOK * 192;
    const bf16* vsrc = g_vp + (size_t)b * 64 * NTOK;

    for (int ic = 0; ic < 64; ic++) {
        __syncthreads();  // prev iter's MMA2 reads of Et/Bt and MMA1 reads of At done
        load_tile(At, qsrc + (size_t)(ic * 64) * 192, 64, 192);
        load_tile(Bt, vsrc + ic * 64, 64, NTOK);
        __syncthreads();
        // MMA1: S[j 32 x i 32] per warp, K=64
        float S[2][4][4];
#pragma unroll
        for (int mt = 0; mt < 2; mt++)
#pragma unroll
            for (int nt = 0; nt < 4; nt++)
#pragma unroll
                for (int e = 0; e < 4; e++) S[mt][nt][e] = 0.f;
        u32 bbase = s2u(At) + (u32)(wn * 32 * LDT * 2) + boff;
#pragma unroll
        for (int ks = 0; ks < 4; ks++) {
            u32 bf[2][4];
#pragma unroll
            for (int np = 0; np < 2; np++)
                ldm4(bf[np], bbase + (u32)((np * 16 * LDT + ks * 16) * 2));
#pragma unroll
            for (int mt = 0; mt < 2; mt++)
#pragma unroll
                for (int np = 0; np < 2; np++) {
                    mma16816(S[mt][2 * np], kA[mt][ks], bf[np][0], bf[np][1]);
                    mma16816(S[mt][2 * np + 1], kA[mt][ks], bf[np][2], bf[np][3]);
                }
        }
        // exp -> bf16 -> Et smem
#pragma unroll
        for (int mt = 0; mt < 2; mt++) {
            int jl = wm * 32 + mt * 16 + (l >> 2);
#pragma unroll
            for (int nt = 0; nt < 4; nt++) {
                int il = wn * 32 + nt * 8 + (l & 3) * 2;
                *(u32*)(Et + jl * LDT + il) =
                    pk_bf2(__expf(S[mt][nt][0]), __expf(S[mt][nt][1]));
                *(u32*)(Et + (jl + 8) * LDT + il) =
                    pk_bf2(__expf(S[mt][nt][2]), __expf(S[mt][nt][3]));
            }
        }
        __syncthreads();
        // MMA2: ya[j 32 x d 32] += Et[j][i] * vp[d][i], K=64 (local i)
        u32 a2 = s2u(Et) + (u32)(wm * 32 * LDT * 2) + aoff;
        u32 b2 = s2u(Bt) + (u32)(wn * 32 * LDT * 2) + boff;
#pragma unroll
        for (int ks = 0; ks < 4; ks++) {
            u32 af[2][4], bf2[2][4];
#pragma unroll
            for (int mt = 0; mt < 2; mt++)
                ldm4(af[mt], a2 + (u32)((mt * 16 * LDT + ks * 16) * 2));
#pragma unroll
            for (int np = 0; np < 2; np++)
                ldm4(bf2[np], b2 + (u32)((np * 16 * LDT + ks * 16) * 2));
#pragma unroll
            for (int mt = 0; mt < 2; mt++)
#pragma unroll
                for (int np = 0; np < 2; np++) {
                    mma16816(ya[mt][2 * np], af[mt], bf2[np][0], bf2[np][1]);
                    mma16816(ya[mt][2 * np + 1], af[mt], bf2[np][2], bf2[np][3]);
                }
        }
    }
    // epilogue: yT[j][d]
#pragma unroll
    for (int mt = 0; mt < 2; mt++)
#pragma unroll
        for (int nt = 0; nt < 4; nt++) {
            int j = j0 + wm * 32 + mt * 16 + (l >> 2);
            int d = wn * 32 + nt * 8 + (l & 3) * 2;
            *(u32*)(g_yT + ((size_t)b * NTOK + j) * 64 + d) =
                pk_bf2(ya[mt][nt][0], ya[mt][nt][1]);
            *(u32*)(g_yT + ((size_t)b * NTOK + j + 8) * 64 + d) =
                pk_bf2(ya[mt][nt][2], ya[mt][nt][3]);
        }
}

// ---------------- k_out ----------------
__global__ void __launch_bounds__(128) k_out(const float* __restrict__ x,
                                             const float* __restrict__ gamma,
                                             float* __restrict__ out) {
    bf16* At = (bf16*)dsm;            // yT tile 128x64 = 18432 B
    bf16* Bt = (bf16*)(dsm + 18432);  // Wo tile  64x64 =  9216 B
    float* Ts = (float*)dsm;          // reused: 64 x 132 f32 = 33792 B
    int j0 = blockIdx.x * 128, o0 = blockIdx.y * 64, b = blockIdx.z;
    int tid = threadIdx.x, wid = tid >> 5, l = tid & 31;
    load_tile(At, g_yT + ((size_t)b * NTOK + j0) * 64, 128, 64);
    load_tile(Bt, g_Wo + o0 * 64, 64, 64);
    __syncthreads();
    float acc[2][8][4];
#pragma unroll
    for (int mt = 0; mt < 2; mt++)
#pragma unroll
        for (int nt = 0; nt < 8; nt++)
#pragma unroll
            for (int e = 0; e < 4; e++) acc[mt][nt][e] = 0.f;
    wmma64<2, 4>(s2u(At) + (u32)(wid * 32 * LDT * 2), s2u(Bt), acc);
    __syncthreads();
#pragma unroll
    for (int mt = 0; mt < 2; mt++)
#pragma unroll
        for (int nt = 0; nt < 8; nt++) {
            int jl = wid * 32 + mt * 16 + (l >> 2);
            int ol = nt * 8 + (l & 3) * 2;
            Ts[ol * 132 + jl] = acc[mt][nt][0];
            Ts[(ol + 1) * 132 + jl] = acc[mt][nt][1];
            Ts[ol * 132 + jl + 8] = acc[mt][nt][2];
            Ts[(ol + 1) * 132 + jl + 8] = acc[mt][nt][3];
        }
    __syncthreads();
    float gm = gamma[0];
    int row = tid >> 1, half = (tid & 1) * 64;
    size_t goff = ((size_t)(b * 256 + o0 + row)) * NTOK + j0 + half;
#pragma unroll
    for (int q = 0; q < 16; q++) {
        float4 s = *(float4*)&Ts[row * 132 + half + q * 4];
        float4 xv = *(const float4*)&x[goff + q * 4];
        float4 o;
        o.x = fmaf(gm, s.x, xv.x);
        o.y = fmaf(gm, s.y, xv.y);
        o.z = fmaf(gm, s.z, xv.z);
        o.w = fmaf(gm, s.w, xv.w);
        *(float4*)&out[goff + q * 4] = o;
    }
}

extern "C" void kernel_launch(void* const* d_in, const int* in_sizes, int n_in,
                              void* d_out, int out_size) {
    const float* v = (const float*)d_in[0];
    const float* Wqkv = (const float*)d_in[1];
    const float* Wout = (const float*)d_in[2];
    const float* gamma = (const float*)d_in[3];
    float* out = (float*)d_out;

    k_prep<<<384, 256>>>(Wqkv, Wout);
    k_xT<<<dim3(64, 4, NB), 256>>>(v);
    k_qkv<<<dim3(32, NB), 256, 18432 + 27648>>>();
    k_lsum<<<dim3(32, NB), 256, 18432>>>();
    k_vp<<<dim3(64, NB), 256>>>();
    k_attn<<<dim3(32, NB), 256, 36864>>>();
    k_out<<<dim3(32, 4, NB), 128, 33792>>>(v, gamma, out);
}

// round 10
// speedup vs baseline: 6.7194x; 1.0420x over previous
#include <cuda_runtime.h>
#include <cuda_bf16.h>
#include <cstdint>
#include <cstddef>

// ConvSelfAttention via mma.sync HMMA bf16 (ptxas target is plain sm_103 -> no tcgen05).
// Flash-style: exp(S) never leaves registers in k_attn; cp.async double-buffering.
//
//  k_prep : Wqkv,Wout -> bf16 ; zero rsum
//  k_xT   : x[b][c][n] -> xT[b][n][c] bf16
//  k_qkv  : qkvT[n][o] = xT @ Wqkv^T            (M=n, N=192, K=256)
//  k_lsum : L[i] = sum_j exp(q_i . k_j)   (Q-frags in regs, pipelined k-tiles)
//  k_vp   : vp[d][i] = val[d][i] / L[i]
//  k_attn : yT[j][d] = sum_i exp(k_j.q_i) * vp[d][i]  (S->exp->A2 all in registers)
//  k_out  : out[o][j] = gamma * (yT @ Wout^T)^T[o][j] + x[o][j]

#define NTOK 4096
#define NB 8
#define LDT 72  // smem row pitch in bf16 (144B, 16B-aligned, ldmatrix conflict-free)

typedef __nv_bfloat16 bf16;
typedef unsigned int u32;

__device__ bf16 g_Wq[192 * 256];                 // [o][c] K-major
__device__ bf16 g_Wo[256 * 64];                  // [o][d] K-major
__device__ bf16 g_xT[(size_t)NB * NTOK * 256];   // [b][n][c]
__device__ bf16 g_qkvT[(size_t)NB * NTOK * 192]; // [b][n][o]  (q|k|v)
__device__ bf16 g_vp[(size_t)NB * 64 * NTOK];    // val/L  [b][d][i]
__device__ bf16 g_yT[(size_t)NB * NTOK * 64];    // [b][j][d]
__device__ float g_rsum[NB * NTOK];              // softmax row sums (atomic)

extern __shared__ char dsm[];

// ---------------- helpers ----------------
__device__ __forceinline__ u32 s2u(const void* p) {
    u32 a;
    asm("{ .reg .u64 t; cvta.to.shared.u64 t, %1; cvt.u32.u64 %0, t; }" : "=r"(a) : "l"(p));
    return a;
}
__device__ __forceinline__ u32 pk_bf2(float lo, float hi) {
    u32 r;
    asm("cvt.rn.bf16x2.f32 %0, %1, %2;" : "=r"(r) : "f"(hi), "f"(lo));
    return r;
}
__device__ __forceinline__ void ldm4(u32* r, u32 addr) {
    asm volatile("ldmatrix.sync.aligned.m8n8.x4.shared.b16 {%0,%1,%2,%3}, [%4];"
                 : "=r"(r[0]), "=r"(r[1]), "=r"(r[2]), "=r"(r[3]) : "r"(addr));
}
__device__ __forceinline__ void mma16816(float* c, const u32* a, u32 b0, u32 b1) {
    asm volatile(
        "mma.sync.aligned.m16n8k16.row.col.f32.bf16.bf16.f32 "
        "{%0,%1,%2,%3}, {%4,%5,%6,%7}, {%8,%9}, {%0,%1,%2,%3};"
        : "+f"(c[0]), "+f"(c[1]), "+f"(c[2]), "+f"(c[3])
        : "r"(a[0]), "r"(a[1]), "r"(a[2]), "r"(a[3]), "r"(b0), "r"(b1));
}
__device__ __forceinline__ u32 a_off(int l) {
    return (u32)((((l & 15) * LDT) + (l >> 4) * 8) * 2);
}
__device__ __forceinline__ u32 b_off(int l) {
    return (u32)(((((l & 7) + ((l >> 4) << 3)) * LDT) + ((l >> 3) & 1) * 8) * 2);
}
__device__ __forceinline__ void cpa16(u32 dst, const void* src) {
    asm volatile("cp.async.ca.shared.global [%0], [%1], 16;" :: "r"(dst), "l"(src));
}
__device__ __forceinline__ void cp_commit() {
    asm volatile("cp.async.commit_group;" ::: "memory");
}
template <int N>
__device__ __forceinline__ void cp_wait() {
    asm volatile("cp.async.wait_group %0;" :: "n"(N) : "memory");
}

// gmem (K-major rows of 64 bf16) -> smem tile with LDT pitch (synchronous)
__device__ __forceinline__ void load_tile(bf16* sm, const bf16* src, int rows, int stride) {
    for (int idx = threadIdx.x; idx < rows * 8; idx += blockDim.x) {
        int r = idx >> 3, c = idx & 7;
        *(uint4*)(sm + r * LDT + c * 8) = *(const uint4*)(src + (size_t)r * stride + c * 8);
    }
}
// async version
__device__ __forceinline__ void load_tile_async(u32 smbase, const bf16* src, int rows,
                                                int stride) {
    for (int idx = threadIdx.x; idx < rows * 8; idx += blockDim.x) {
        int r = idx >> 3, c = idx & 7;
        cpa16(smbase + (u32)((r * LDT + c * 8) * 2), src + (size_t)r * stride + c * 8);
    }
}

// Warp GEMM over one K=64 smem chunk (A and B both from smem).
template <int MT, int NTP>
__device__ __forceinline__ void wmma64(u32 sA, u32 sB, float (&acc)[MT][2 * NTP][4]) {
    const int l = threadIdx.x & 31;
    const u32 aoff = a_off(l), boff = b_off(l);
#pragma unroll
    for (int ks = 0; ks < 4; ks++) {
        u32 a[MT][4], b[NTP][4];
#pragma unroll
        for (int mt = 0; mt < MT; mt++)
            ldm4(a[mt], sA + aoff + (u32)((mt * 16 * LDT + ks * 16) * 2));
#pragma unroll
        for (int np = 0; np < NTP; np++)
            ldm4(b[np], sB + boff + (u32)((np * 16 * LDT + ks * 16) * 2));
#pragma unroll
        for (int mt = 0; mt < MT; mt++)
#pragma unroll
            for (int np = 0; np < NTP; np++) {
                mma16816(acc[mt][2 * np], a[mt], b[np][0], b[np][1]);
                mma16816(acc[mt][2 * np + 1], a[mt], b[np][2], b[np][3]);
            }
    }
}

// ---------------- k_prep ----------------
__global__ void k_prep(const float* __restrict__ Wqkv, const float* __restrict__ Wout) {
    int idx = blockIdx.x * 256 + threadIdx.x;
    if (idx < 192 * 256) {
        g_Wq[idx] = __float2bfloat16(Wqkv[idx]);
    } else if (idx < 192 * 256 + 256 * 64) {
        int j = idx - 192 * 256;
        g_Wo[j] = __float2bfloat16(Wout[j]);
    } else {
        int j = idx - (192 * 256 + 256 * 64);
        if (j < NB * NTOK) g_rsum[j] = 0.0f;
    }
}

// ---------------- k_xT ----------------
__global__ void __launch_bounds__(256) k_xT(const float* __restrict__ x) {
    __shared__ float sv[64][65];
    int b = blockIdx.z, c0 = blockIdx.y * 64, n0 = blockIdx.x * 64;
    for (int lin = threadIdx.x; lin < 4096; lin += 256) {
        int cl = lin >> 6, nl = lin & 63;
        sv[cl][nl] = x[((size_t)(b * 256 + c0 + cl)) * NTOK + n0 + nl];
    }
    __syncthreads();
    for (int lin = threadIdx.x; lin < 4096; lin += 256) {
        int nl = lin >> 6, cl = lin & 63;
        g_xT[((size_t)b * NTOK + n0 + nl) * 256 + c0 + cl] = __float2bfloat16(sv[cl][nl]);
    }
}

// ---------------- k_qkv ----------------
__global__ void __launch_bounds__(256) k_qkv() {
    bf16* At = (bf16*)dsm;            // 128 x 64 (pitch 72) = 18432 B
    bf16* Bt = (bf16*)(dsm + 18432);  // 192 x 64            = 27648 B
    int b = blockIdx.y, n0 = blockIdx.x * 128;
    int tid = threadIdx.x, wid = tid >> 5, l = tid & 31;
    int wm = wid & 3, wn = wid >> 2;
    float acc[2][12][4];
#pragma unroll
    for (int mt = 0; mt < 2; mt++)
#pragma unroll
        for (int nt = 0; nt < 12; nt++)
#pragma unroll
            for (int e = 0; e < 4; e++) acc[mt][nt][e] = 0.f;

    const bf16* asrc = g_xT + ((size_t)b * NTOK + n0) * 256;
    for (int kc = 0; kc < 4; kc++) {
        __syncthreads();
        load_tile(At, asrc + kc * 64, 128, 256);
        load_tile(Bt, g_Wq + kc * 64, 192, 256);
        __syncthreads();
        wmma64<2, 6>(s2u(At) + (u32)(wm * 32 * LDT * 2),
                     s2u(Bt) + (u32)(wn * 96 * LDT * 2), acc);
    }
#pragma unroll
    for (int mt = 0; mt < 2; mt++)
#pragma unroll
        for (int nt = 0; nt < 12; nt++) {
            int j = n0 + wm * 32 + mt * 16 + (l >> 2);
            int o = wn * 96 + nt * 8 + (l & 3) * 2;
            *(u32*)(g_qkvT + ((size_t)b * NTOK + j) * 192 + o) =
                pk_bf2(acc[mt][nt][0], acc[mt][nt][1]);
            *(u32*)(g_qkvT + ((size_t)b * NTOK + j + 8) * 192 + o) =
                pk_bf2(acc[mt][nt][2], acc[mt][nt][3]);
        }
}

// ---------------- k_lsum: L[i] = sum_j exp(q_i . k_j), pipelined ----------------
__global__ void __launch_bounds__(256, 1) k_lsum() {
    u32 kb[2] = {s2u(dsm), s2u(dsm) + 18432};  // two 128x72 bf16 tiles
    int b = blockIdx.y, i0 = blockIdx.x * 128;
    int tid = threadIdx.x, wid = tid >> 5, l = tid & 31;
    int wm = wid & 3, wn = wid >> 2;  // wm: i-warp (4x32), wn: j-half (2x64)

    const bf16* qsrc = g_qkvT + ((size_t)b * NTOK + i0) * 192;
    const bf16* ksrc = g_qkvT + (size_t)b * NTOK * 192 + 64;

    // stage q i-tile into kb0, capture A fragments
    load_tile_async(kb[0], qsrc, 128, 192);
    cp_commit();
    cp_wait<0>();
    __syncthreads();
    u32 qA[2][4][4];
    {
        u32 base = kb[0] + (u32)(wm * 32 * LDT * 2) + a_off(l);
#pragma unroll
        for (int mt = 0; mt < 2; mt++)
#pragma unroll
            for (int ks = 0; ks < 4; ks++)
                ldm4(qA[mt][ks], base + (u32)((mt * 16 * LDT + ks * 16) * 2));
    }
    __syncthreads();  // all warps done reading q from kb0

    // prefetch k-tiles 0 and 1  (k_jt lives in kb[(jt+1)&1])
    load_tile_async(kb[1], ksrc, 128, 192);
    cp_commit();
    load_tile_async(kb[0], ksrc + (size_t)128 * 192, 128, 192);
    cp_commit();

    float rs[2][2] = {{0.f, 0.f}, {0.f, 0.f}};
    const u32 boff = b_off(l);

    for (int jt = 0; jt < 32; jt++) {
        if (jt < 31) cp_wait<1>();
        else cp_wait<0>();
        __syncthreads();
        u32 kcur = kb[(jt + 1) & 1];
        float S[2][8][4];
#pragma unroll
        for (int mt = 0; mt < 2; mt++)
#pragma unroll
            for (int nt = 0; nt < 8; nt++)
#pragma unroll
                for (int e = 0; e < 4; e++) S[mt][nt][e] = 0.f;
        u32 bbase = kcur + (u32)(wn * 64 * LDT * 2) + boff;
#pragma unroll
        for (int ks = 0; ks < 4; ks++) {
            u32 bf[4][4];
#pragma unroll
            for (int np = 0; np < 4; np++)
                ldm4(bf[np], bbase + (u32)((np * 16 * LDT + ks * 16) * 2));
#pragma unroll
            for (int mt = 0; mt < 2; mt++)
#pragma unroll
                for (int np = 0; np < 4; np++) {
                    mma16816(S[mt][2 * np], qA[mt][ks], bf[np][0], bf[np][1]);
                    mma16816(S[mt][2 * np + 1], qA[mt][ks], bf[np][2], bf[np][3]);
                }
        }
#pragma unroll
        for (int mt = 0; mt < 2; mt++)
#pragma unroll
            for (int nt = 0; nt < 8; nt++) {
                rs[mt][0] += __expf(S[mt][nt][0]) + __expf(S[mt][nt][1]);
                rs[mt][1] += __expf(S[mt][nt][2]) + __expf(S[mt][nt][3]);
            }
        __syncthreads();  // done reading kcur; safe to overwrite
        if (jt + 2 < 32) {
            load_tile_async(kcur, ksrc + (size_t)((jt + 2) * 128) * 192, 128, 192);
            cp_commit();
        }
    }
#pragma unroll
    for (int mt = 0; mt < 2; mt++)
#pragma unroll
        for (int h = 0; h < 2; h++) {
            float s = rs[mt][h];
            s += __shfl_xor_sync(0xffffffffu, s, 1);
            s += __shfl_xor_sync(0xffffffffu, s, 2);
            if ((l & 3) == 0)
                atomicAdd(&g_rsum[b * NTOK + i0 + wm * 32 + mt * 16 + (l >> 2) + h * 8], s);
        }
}

// ---------------- k_vp: vp[d][i] = val[d][i] / L[i] ----------------
__global__ void __launch_bounds__(256) k_vp() {
    __shared__ float sv[64][65];
    int b = blockIdx.y, n0 = blockIdx.x * 64;
    for (int lin = threadIdx.x; lin < 4096; lin += 256) {
        int nl = lin >> 6, dl = lin & 63;
        sv[nl][dl] =
            __bfloat162float(g_qkvT[((size_t)b * NTOK + n0 + nl) * 192 + 128 + dl]);
    }
    __syncthreads();
    for (int lin = threadIdx.x; lin < 4096; lin += 256) {
        int nl = lin & 63, dl = lin >> 6;
        float li = 1.0f / g_rsum[b * NTOK + n0 + nl];
        g_vp[((size_t)(b * 64 + dl)) * NTOK + n0 + nl] = __float2bfloat16(sv[nl][dl] * li);
    }
}

// ---------------- k_attn: yT[j][d] = sum_i exp(k_j.q_i) vp[d][i] ----------------
// Two stages, each = q chunk (64x72, 9216B) + vp chunk (64x72, 9216B).
// S fragments -> exp -> MMA2 A-operand entirely in registers.
__global__ void __launch_bounds__(256, 1) k_attn() {
    u32 st[2] = {s2u(dsm), s2u(dsm) + 18432};
    int b = blockIdx.y, j0 = blockIdx.x * 128;
    int tid = threadIdx.x, wid = tid >> 5, l = tid & 31;
    int wm = wid & 3, wn = wid >> 2;  // wm: j-warp (4x32); wn: i-half (2x32)

    const bf16* ksrc = g_qkvT + ((size_t)b * NTOK + j0) * 192 + 64;
    const bf16* qsrc = g_qkvT + (size_t)b * NTOK * 192;
    const bf16* vsrc = g_vp + (size_t)b * 64 * NTOK;

    // stage kT j-tile into st0 (full 128 rows = 18432B), capture A fragments
    load_tile_async(st[0], ksrc, 128, 192);
    cp_commit();
    cp_wait<0>();
    __syncthreads();
    u32 kA[2][4][4];
    {
        u32 base = st[0] + (u32)(wm * 32 * LDT * 2) + a_off(l);
#pragma unroll
        for (int mt = 0; mt < 2; mt++)
#pragma unroll
            for (int ks = 0; ks < 4; ks++)
                ldm4(kA[mt][ks], base + (u32)((mt * 16 * LDT + ks * 16) * 2));
    }
    __syncthreads();

    // prefetch stages for ic 0 and 1  (chunk ic lives in st[(ic+1)&1])
    load_tile_async(st[1], qsrc, 64, 192);
    load_tile_async(st[1] + 9216, vsrc, 64, NTOK);
    cp_commit();
    load_tile_async(st[0], qsrc + (size_t)64 * 192, 64, 192);
    load_tile_async(st[0] + 9216, vsrc + 64, 64, NTOK);
    cp_commit();

    float ya[2][8][4];
#pragma unroll
    for (int mt = 0; mt < 2; mt++)
#pragma unroll
        for (int nt = 0; nt < 8; nt++)
#pragma unroll
            for (int e = 0; e < 4; e++) ya[mt][nt][e] = 0.f;

    const u32 boff = b_off(l);

    for (int ic = 0; ic < 64; ic++) {
        if (ic < 63) cp_wait<1>();
        else cp_wait<0>();
        __syncthreads();
        u32 cur = st[(ic + 1) & 1];
        // MMA1: S[j 32 x i 32] per warp, K=64 over d
        float S[2][4][4];
#pragma unroll
        for (int mt = 0; mt < 2; mt++)
#pragma unroll
            for (int nt = 0; nt < 4; nt++)
#pragma unroll
                for (int e = 0; e < 4; e++) S[mt][nt][e] = 0.f;
        u32 qb = cur + (u32)(wn * 32 * LDT * 2) + boff;
#pragma unroll
        for (int ks = 0; ks < 4; ks++) {
            u32 bq[2][4];
#pragma unroll
            for (int np = 0; np < 2; np++)
                ldm4(bq[np], qb + (u32)((np * 16 * LDT + ks * 16) * 2));
#pragma unroll
            for (int mt = 0; mt < 2; mt++)
#pragma unroll
                for (int np = 0; np < 2; np++) {
                    mma16816(S[mt][2 * np], kA[mt][ks], bq[np][0], bq[np][1]);
                    mma16816(S[mt][2 * np + 1], kA[mt][ks], bq[np][2], bq[np][3]);
                }
        }
        // exp in registers, repack C-fragments as A-fragments (m16k16 over local i)
        u32 A2[2][2][4];
#pragma unroll
        for (int mt = 0; mt < 2; mt++)
#pragma unroll
            for (int k2 = 0; k2 < 2; k2++) {
                const float* s0 = S[mt][2 * k2];
                const float* s1 = S[mt][2 * k2 + 1];
                A2[mt][k2][0] = pk_bf2(__expf(s0[0]), __expf(s0[1]));
                A2[mt][k2][1] = pk_bf2(__expf(s0[2]), __expf(s0[3]));
                A2[mt][k2][2] = pk_bf2(__expf(s1[0]), __expf(s1[1]));
                A2[mt][k2][3] = pk_bf2(__expf(s1[2]), __expf(s1[3]));
            }
        // MMA2: ya[j 32 x d 64] += E[j][i32] * vp[d][i32]
        u32 vb = cur + 9216 + boff;
#pragma unroll
        for (int k2 = 0; k2 < 2; k2++) {
            u32 bv[4][4];
#pragma unroll
            for (int np = 0; np < 4; np++)
                ldm4(bv[np], vb + (u32)((np * 16 * LDT + wn * 32 + k2 * 16) * 2));
#pragma unroll
            for (int mt = 0; mt < 2; mt++)
#pragma unroll
                for (int np = 0; np < 4; np++) {
                    mma16816(ya[mt][2 * np], A2[mt][k2], bv[np][0], bv[np][1]);
                    mma16816(ya[mt][2 * np + 1], A2[mt][k2], bv[np][2], bv[np][3]);
                }
        }
        __syncthreads();  // done reading cur; safe to overwrite
        if (ic + 2 < 64) {
            load_tile_async(cur, qsrc + (size_t)((ic + 2) * 64) * 192, 64, 192);
            load_tile_async(cur + 9216, vsrc + (ic + 2) * 64, 64, NTOK);
            cp_commit();
        }
    }

    // epilogue: reduce the two wn i-halves via smem, write bf16 yT
    __syncthreads();
    float* red = (float*)dsm;  // 4 regions of 32x66 f32 = 33792 B
    const int r0 = l >> 2, c0 = (l & 3) * 2;
    if (wn == 0) {
#pragma unroll
        for (int mt = 0; mt < 2; mt++)
#pragma unroll
            for (int np = 0; np < 4; np++)
#pragma unroll
                for (int h = 0; h < 2; h++) {
                    int nt = 2 * np + h;
                    float* p = red + wm * 2112 + (mt * 16 + r0) * 66 + np * 16 + h * 8 + c0;
                    p[0] = ya[mt][nt][0];
                    p[1] = ya[mt][nt][1];
                    p[8 * 66] = ya[mt][nt][2];
                    p[8 * 66 + 1] = ya[mt][nt][3];
                }
    }
    __syncthreads();
    if (wn == 1) {
#pragma unroll
        for (int mt = 0; mt < 2; mt++)
#pragma unroll
            for (int np = 0; np < 4; np++)
#pragma unroll
                for (int h = 0; h < 2; h++) {
                    int nt = 2 * np + h;
                    const float* p =
                        red + wm * 2112 + (mt * 16 + r0) * 66 + np * 16 + h * 8 + c0;
                    int j = j0 + wm * 32 + mt * 16 + r0;
                    int d = np * 16 + h * 8 + c0;
                    *(u32*)(g_yT + ((size_t)b * NTOK + j) * 64 + d) =
                        pk_bf2(ya[mt][nt][0] + p[0], ya[mt][nt][1] + p[1]);
                    *(u32*)(g_yT + ((size_t)b * NTOK + j + 8) * 64 + d) =
                        pk_bf2(ya[mt][nt][2] + p[8 * 66], ya[mt][nt][3] + p[8 * 66 + 1]);
                }
    }
}

// ---------------- k_out ----------------
__global__ void __launch_bounds__(128) k_out(const float* __restrict__ x,
                                             const float* __restrict__ gamma,
                                             float* __restrict__ out) {
    bf16* At = (bf16*)dsm;            // yT tile 128x64 = 18432 B
    bf16* Bt = (bf16*)(dsm + 18432);  // Wo tile  64x64 =  9216 B
    float* Ts = (float*)dsm;          // reused: 64 x 132 f32 = 33792 B
    int j0 = blockIdx.x * 128, o0 = blockIdx.y * 64, b = blockIdx.z;
    int tid = threadIdx.x, wid = tid >> 5, l = tid & 31;
    load_tile(At, g_yT + ((size_t)b * NTOK + j0) * 64, 128, 64);
    load_tile(Bt, g_Wo + o0 * 64, 64, 64);
    __syncthreads();
    float acc[2][8][4];
#pragma unroll
    for (int mt = 0; mt < 2; mt++)
#pragma unroll
        for (int nt = 0; nt < 8; nt++)
#pragma unroll
            for (int e = 0; e < 4; e++) acc[mt][nt][e] = 0.f;
    wmma64<2, 4>(s2u(At) + (u32)(wid * 32 * LDT * 2), s2u(Bt), acc);
    __syncthreads();
#pragma unroll
    for (int mt = 0; mt < 2; mt++)
#pragma unroll
        for (int nt = 0; nt < 8; nt++) {
            int jl = wid * 32 + mt * 16 + (l >> 2);
            int ol = nt * 8 + (l & 3) * 2;
            Ts[ol * 132 + jl] = acc[mt][nt][0];
            Ts[(ol + 1) * 132 + jl] = acc[mt][nt][1];
            Ts[ol * 132 + jl + 8] = acc[mt][nt][2];
            Ts[(ol + 1) * 132 + jl + 8] = acc[mt][nt][3];
        }
    __syncthreads();
    float gm = gamma[0];
    int row = tid >> 1, half = (tid & 1) * 64;
    size_t goff = ((size_t)(b * 256 + o0 + row)) * NTOK + j0 + half;
#pragma unroll
    for (int q = 0; q < 16; q++) {
        float4 s = *(float4*)&Ts[row * 132 + half + q * 4];
        float4 xv = *(const float4*)&x[goff + q * 4];
        float4 o;
        o.x = fmaf(gm, s.x, xv.x);
        o.y = fmaf(gm, s.y, xv.y);
        o.z = fmaf(gm, s.z, xv.z);
        o.w = fmaf(gm, s.w, xv.w);
        *(float4*)&out[goff + q * 4] = o;
    }
}

extern "C" void kernel_launch(void* const* d_in, const int* in_sizes, int n_in,
                              void* d_out, int out_size) {
    const float* v = (const float*)d_in[0];
    const float* Wqkv = (const float*)d_in[1];
    const float* Wout = (const float*)d_in[2];
    const float* gamma = (const float*)d_in[3];
    float* out = (float*)d_out;

    k_prep<<<384, 256>>>(Wqkv, Wout);
    k_xT<<<dim3(64, 4, NB), 256>>>(v);
    k_qkv<<<dim3(32, NB), 256, 18432 + 27648>>>();
    k_lsum<<<dim3(32, NB), 256, 36864>>>();
    k_vp<<<dim3(64, NB), 256>>>();
    k_attn<<<dim3(32, NB), 256, 36864>>>();
    k_out<<<dim3(32, 4, NB), 128, 33792>>>(v, gamma, out);
}

// round 13
// speedup vs baseline: 7.8019x; 1.1611x over previous
#include <cuda_runtime.h>
#include <cuda_bf16.h>
#include <cstdint>
#include <cstddef>

// ConvSelfAttention via mma.sync HMMA bf16 (ptxas target is plain sm_103 -> no tcgen05).
// Flash-style: exp(S) never leaves registers in k_attn; cp.async double-buffering;
// register footprints sized for 2 CTAs/SM on the two attention kernels.
//
//  k_prep : Wqkv,Wout -> bf16 ; zero rsum
//  k_xT   : x[b][c][n] -> xT[b][n][c] bf16
//  k_qkv  : qkvT[n][o] = xT @ Wqkv^T            (M=n, N=192, K=256)
//  k_lsum : L[i] = sum_j exp(q_i . k_j)   (Q-frags in regs, pipelined k-tiles)
//  k_vp   : vp[d][i] = val[d][i] / L[i]
//  k_attn : yT[j][d] = sum_i exp(k_j.q_i) * vp[d][i]  (S->exp->A2 in registers,
//           8 warps x disjoint 16j x 64d output tiles)
//  k_out  : out[o][j] = gamma * (yT @ Wout^T)^T[o][j] + x[o][j]

#define NTOK 4096
#define NB 8
#define LDT 72  // smem row pitch in bf16 (144B, 16B-aligned, ldmatrix conflict-free)

typedef __nv_bfloat16 bf16;
typedef unsigned int u32;

__device__ bf16 g_Wq[192 * 256];                 // [o][c] K-major
__device__ bf16 g_Wo[256 * 64];                  // [o][d] K-major
__device__ bf16 g_xT[(size_t)NB * NTOK * 256];   // [b][n][c]
__device__ bf16 g_qkvT[(size_t)NB * NTOK * 192]; // [b][n][o]  (q|k|v)
__device__ bf16 g_vp[(size_t)NB * 64 * NTOK];    // val/L  [b][d][i]
__device__ bf16 g_yT[(size_t)NB * NTOK * 64];    // [b][j][d]
__device__ float g_rsum[NB * NTOK];              // softmax row sums (atomic)

extern __shared__ char dsm[];

// ---------------- helpers ----------------
__device__ __forceinline__ u32 s2u(const void* p) {
    u32 a;
    asm("{ .reg .u64 t; cvta.to.shared.u64 t, %1; cvt.u32.u64 %0, t; }" : "=r"(a) : "l"(p));
    return a;
}
__device__ __forceinline__ u32 pk_bf2(float lo, float hi) {
    u32 r;
    asm("cvt.rn.bf16x2.f32 %0, %1, %2;" : "=r"(r) : "f"(hi), "f"(lo));
    return r;
}
__device__ __forceinline__ void ldm4(u32* r, u32 addr) {
    asm volatile("ldmatrix.sync.aligned.m8n8.x4.shared.b16 {%0,%1,%2,%3}, [%4];"
                 : "=r"(r[0]), "=r"(r[1]), "=r"(r[2]), "=r"(r[3]) : "r"(addr));
}
__device__ __forceinline__ void mma16816(float* c, const u32* a, u32 b0, u32 b1) {
    asm volatile(
        "mma.sync.aligned.m16n8k16.row.col.f32.bf16.bf16.f32 "
        "{%0,%1,%2,%3}, {%4,%5,%6,%7}, {%8,%9}, {%0,%1,%2,%3};"
        : "+f"(c[0]), "+f"(c[1]), "+f"(c[2]), "+f"(c[3])
        : "r"(a[0]), "r"(a[1]), "r"(a[2]), "r"(a[3]), "r"(b0), "r"(b1));
}
__device__ __forceinline__ u32 a_off(int l) {
    return (u32)((((l & 15) * LDT) + (l >> 4) * 8) * 2);
}
__device__ __forceinline__ u32 b_off(int l) {
    return (u32)(((((l & 7) + ((l >> 4) << 3)) * LDT) + ((l >> 3) & 1) * 8) * 2);
}
__device__ __forceinline__ void cpa16(u32 dst, const void* src) {
    asm volatile("cp.async.ca.shared.global [%0], [%1], 16;" :: "r"(dst), "l"(src));
}
__device__ __forceinline__ void cp_commit() {
    asm volatile("cp.async.commit_group;" ::: "memory");
}
template <int N>
__device__ __forceinline__ void cp_wait() {
    asm volatile("cp.async.wait_group %0;" :: "n"(N) : "memory");
}

// gmem (K-major rows of 64 bf16) -> smem tile with LDT pitch (synchronous)
__device__ __forceinline__ void load_tile(bf16* sm, const bf16* src, int rows, int stride) {
    for (int idx = threadIdx.x; idx < rows * 8; idx += blockDim.x) {
        int r = idx >> 3, c = idx & 7;
        *(uint4*)(sm + r * LDT + c * 8) = *(const uint4*)(src + (size_t)r * stride + c * 8);
    }
}
// async version
__device__ __forceinline__ void load_tile_async(u32 smbase, const bf16* src, int rows,
                                                int stride) {
    for (int idx = threadIdx.x; idx < rows * 8; idx += blockDim.x) {
        int r = idx >> 3, c = idx & 7;
        cpa16(smbase + (u32)((r * LDT + c * 8) * 2), src + (size_t)r * stride + c * 8);
    }
}

// Warp GEMM over one K=64 smem chunk (A and B both from smem).
template <int MT, int NTP>
__device__ __forceinline__ void wmma64(u32 sA, u32 sB, float (&acc)[MT][2 * NTP][4]) {
    const int l = threadIdx.x & 31;
    const u32 aoff = a_off(l), boff = b_off(l);
#pragma unroll
    for (int ks = 0; ks < 4; ks++) {
        u32 a[MT][4], b[NTP][4];
#pragma unroll
        for (int mt = 0; mt < MT; mt++)
            ldm4(a[mt], sA + aoff + (u32)((mt * 16 * LDT + ks * 16) * 2));
#pragma unroll
        for (int np = 0; np < NTP; np++)
            ldm4(b[np], sB + boff + (u32)((np * 16 * LDT + ks * 16) * 2));
#pragma unroll
        for (int mt = 0; mt < MT; mt++)
#pragma unroll
            for (int np = 0; np < NTP; np++) {
                mma16816(acc[mt][2 * np], a[mt], b[np][0], b[np][1]);
                mma16816(acc[mt][2 * np + 1], a[mt], b[np][2], b[np][3]);
            }
    }
}

// ---------------- k_prep ----------------
__global__ void k_prep(const float* __restrict__ Wqkv, const float* __restrict__ Wout) {
    int idx = blockIdx.x * 256 + threadIdx.x;
    if (idx < 192 * 256) {
        g_Wq[idx] = __float2bfloat16(Wqkv[idx]);
    } else if (idx < 192 * 256 + 256 * 64) {
        int j = idx - 192 * 256;
        g_Wo[j] = __float2bfloat16(Wout[j]);
    } else {
        int j = idx - (192 * 256 + 256 * 64);
        if (j < NB * NTOK) g_rsum[j] = 0.0f;
    }
}

// ---------------- k_xT ----------------
__global__ void __launch_bounds__(256) k_xT(const float* __restrict__ x) {
    __shared__ float sv[64][65];
    int b = blockIdx.z, c0 = blockIdx.y * 64, n0 = blockIdx.x * 64;
    for (int lin = threadIdx.x; lin < 4096; lin += 256) {
        int cl = lin >> 6, nl = lin & 63;
        sv[cl][nl] = x[((size_t)(b * 256 + c0 + cl)) * NTOK + n0 + nl];
    }
    __syncthreads();
    for (int lin = threadIdx.x; lin < 4096; lin += 256) {
        int nl = lin >> 6, cl = lin & 63;
        g_xT[((size_t)b * NTOK + n0 + nl) * 256 + c0 + cl] = __float2bfloat16(sv[cl][nl]);
    }
}

// ---------------- k_qkv ----------------
__global__ void __launch_bounds__(256) k_qkv() {
    bf16* At = (bf16*)dsm;            // 128 x 64 (pitch 72) = 18432 B
    bf16* Bt = (bf16*)(dsm + 18432);  // 192 x 64            = 27648 B
    int b = blockIdx.y, n0 = blockIdx.x * 128;
    int tid = threadIdx.x, wid = tid >> 5, l = tid & 31;
    int wm = wid & 3, wn = wid >> 2;
    float acc[2][12][4];
#pragma unroll
    for (int mt = 0; mt < 2; mt++)
#pragma unroll
        for (int nt = 0; nt < 12; nt++)
#pragma unroll
            for (int e = 0; e < 4; e++) acc[mt][nt][e] = 0.f;

    const bf16* asrc = g_xT + ((size_t)b * NTOK + n0) * 256;
    for (int kc = 0; kc < 4; kc++) {
        __syncthreads();
        load_tile(At, asrc + kc * 64, 128, 256);
        load_tile(Bt, g_Wq + kc * 64, 192, 256);
        __syncthreads();
        wmma64<2, 6>(s2u(At) + (u32)(wm * 32 * LDT * 2),
                     s2u(Bt) + (u32)(wn * 96 * LDT * 2), acc);
    }
#pragma unroll
    for (int mt = 0; mt < 2; mt++)
#pragma unroll
        for (int nt = 0; nt < 12; nt++) {
            int j = n0 + wm * 32 + mt * 16 + (l >> 2);
            int o = wn * 96 + nt * 8 + (l & 3) * 2;
            *(u32*)(g_qkvT + ((size_t)b * NTOK + j) * 192 + o) =
                pk_bf2(acc[mt][nt][0], acc[mt][nt][1]);
            *(u32*)(g_qkvT + ((size_t)b * NTOK + j + 8) * 192 + o) =
                pk_bf2(acc[mt][nt][2], acc[mt][nt][3]);
        }
}

// ---------------- k_lsum: L[i] = sum_j exp(q_i . k_j), pipelined, 2 CTA/SM --------
__global__ void __launch_bounds__(256, 2) k_lsum() {
    u32 kb[2] = {s2u(dsm), s2u(dsm) + 18432};  // two 128x72 bf16 tiles
    int b = blockIdx.y, i0 = blockIdx.x * 128;
    int tid = threadIdx.x, wid = tid >> 5, l = tid & 31;
    int wm = wid & 3, wn = wid >> 2;  // wm: i-warp (4x32), wn: j-half (2x64)

    const bf16* qsrc = g_qkvT + ((size_t)b * NTOK + i0) * 192;
    const bf16* ksrc = g_qkvT + (size_t)b * NTOK * 192 + 64;

    // stage q i-tile into kb0, capture A fragments
    load_tile_async(kb[0], qsrc, 128, 192);
    cp_commit();
    cp_wait<0>();
    __syncthreads();
    u32 qA[2][4][4];
    {
        u32 base = kb[0] + (u32)(wm * 32 * LDT * 2) + a_off(l);
#pragma unroll
        for (int mt = 0; mt < 2; mt++)
#pragma unroll
            for (int ks = 0; ks < 4; ks++)
                ldm4(qA[mt][ks], base + (u32)((mt * 16 * LDT + ks * 16) * 2));
    }
    __syncthreads();  // all warps done reading q from kb0

    // prefetch k-tiles 0 and 1  (k_jt lives in kb[(jt+1)&1])
    load_tile_async(kb[1], ksrc, 128, 192);
    cp_commit();
    load_tile_async(kb[0], ksrc + (size_t)128 * 192, 128, 192);
    cp_commit();

    float rs[2][2] = {{0.f, 0.f}, {0.f, 0.f}};
    const u32 boff = b_off(l);

    for (int jt = 0; jt < 32; jt++) {
        if (jt < 31) cp_wait<1>();
        else cp_wait<0>();
        __syncthreads();
        u32 kcur = kb[(jt + 1) & 1];
        // sub-loop j 32-wide: S footprint stays at 32 regs
#pragma unroll
        for (int js = 0; js < 2; js++) {
            float S[2][4][4];
#pragma unroll
            for (int mt = 0; mt < 2; mt++)
#pragma unroll
                for (int nt = 0; nt < 4; nt++)
#pragma unroll
                    for (int e = 0; e < 4; e++) S[mt][nt][e] = 0.f;
            u32 bbase = kcur + (u32)((wn * 64 + js * 32) * LDT * 2) + boff;
#pragma unroll
            for (int ks = 0; ks < 4; ks++) {
                u32 bf[2][4];
#pragma unroll
                for (int np = 0; np < 2; np++)
                    ldm4(bf[np], bbase + (u32)((np * 16 * LDT + ks * 16) * 2));
#pragma unroll
                for (int mt = 0; mt < 2; mt++)
#pragma unroll
                    for (int np = 0; np < 2; np++) {
                        mma16816(S[mt][2 * np], qA[mt][ks], bf[np][0], bf[np][1]);
                        mma16816(S[mt][2 * np + 1], qA[mt][ks], bf[np][2], bf[np][3]);
                    }
            }
#pragma unroll
            for (int mt = 0; mt < 2; mt++)
#pragma unroll
                for (int nt = 0; nt < 4; nt++) {
                    rs[mt][0] += __expf(S[mt][nt][0]) + __expf(S[mt][nt][1]);
                    rs[mt][1] += __expf(S[mt][nt][2]) + __expf(S[mt][nt][3]);
                }
        }
        __syncthreads();  // done reading kcur; safe to overwrite
        if (jt + 2 < 32) {
            load_tile_async(kcur, ksrc + (size_t)((jt + 2) * 128) * 192, 128, 192);
            cp_commit();
        }
    }
#pragma unroll
    for (int mt = 0; mt < 2; mt++)
#pragma unroll
        for (int h = 0; h < 2; h++) {
            float s = rs[mt][h];
            s += __shfl_xor_sync(0xffffffffu, s, 1);
            s += __shfl_xor_sync(0xffffffffu, s, 2);
            if ((l & 3) == 0)
                atomicAdd(&g_rsum[b * NTOK + i0 + wm * 32 + mt * 16 + (l >> 2) + h * 8], s);
        }
}

// ---------------- k_vp: vp[d][i] = val[d][i] / L[i] ----------------
__global__ void __launch_bounds__(256) k_vp() {
    __shared__ float sv[64][65];
    int b = blockIdx.y, n0 = blockIdx.x * 64;
    for (int lin = threadIdx.x; lin < 4096; lin += 256) {
        int nl = lin >> 6, dl = lin & 63;
        sv[nl][dl] =
            __bfloat162float(g_qkvT[((size_t)b * NTOK + n0 + nl) * 192 + 128 + dl]);
    }
    __syncthreads();
    for (int lin = threadIdx.x; lin < 4096; lin += 256) {
        int nl = lin & 63, dl = lin >> 6;
        float li = 1.0f / g_rsum[b * NTOK + n0 + nl];
        g_vp[((size_t)(b * 64 + dl)) * NTOK + n0 + nl] = __float2bfloat16(sv[nl][dl] * li);
    }
}

// ---------------- k_attn: yT[j][d] = sum_i exp(k_j.q_i) vp[d][i] ----------------
// 8 warps x disjoint 16j x 64d output tiles; each warp covers the full 64-i chunk.
// S -> exp -> MMA2 A-operand entirely in registers; no cross-warp reduction.
__global__ void __launch_bounds__(256, 2) k_attn() {
    u32 st[2] = {s2u(dsm), s2u(dsm) + 18432};
    int b = blockIdx.y, j0 = blockIdx.x * 128;
    int tid = threadIdx.x, wid = tid >> 5, l = tid & 31;

    const bf16* ksrc = g_qkvT + ((size_t)b * NTOK + j0) * 192 + 64;
    const bf16* qsrc = g_qkvT + (size_t)b * NTOK * 192;
    const bf16* vsrc = g_vp + (size_t)b * 64 * NTOK;

    // stage kT j-tile into st0 (128 rows), capture A fragments (16 j-rows per warp)
    load_tile_async(st[0], ksrc, 128, 192);
    cp_commit();
    cp_wait<0>();
    __syncthreads();
    u32 kA[4][4];
    {
        u32 base = st[0] + (u32)(wid * 16 * LDT * 2) + a_off(l);
#pragma unroll
        for (int ks = 0; ks < 4; ks++) ldm4(kA[ks], base + (u32)((ks * 16) * 2));
    }
    __syncthreads();

    // prefetch stages for ic 0 and 1  (chunk ic lives in st[(ic+1)&1])
    load_tile_async(st[1], qsrc, 64, 192);
    load_tile_async(st[1] + 9216, vsrc, 64, NTOK);
    cp_commit();
    load_tile_async(st[0], qsrc + (size_t)64 * 192, 64, 192);
    load_tile_async(st[0] + 9216, vsrc + 64, 64, NTOK);
    cp_commit();

    float ya[8][4];
#pragma unroll
    for (int nt = 0; nt < 8; nt++)
#pragma unroll
        for (int e = 0; e < 4; e++) ya[nt][e] = 0.f;

    const u32 boff = b_off(l);

    for (int ic = 0; ic < 64; ic++) {
        if (ic < 63) cp_wait<1>();
        else cp_wait<0>();
        __syncthreads();
        u32 cur = st[(ic + 1) & 1];
        // MMA1: S[16j x 64i], K=64 over d
        float S[8][4];
#pragma unroll
        for (int nt = 0; nt < 8; nt++)
#pragma unroll
            for (int e = 0; e < 4; e++) S[nt][e] = 0.f;
        u32 qb = cur + boff;
#pragma unroll
        for (int ks = 0; ks < 4; ks++) {
            u32 bq[4][4];
#pragma unroll
            for (int np = 0; np < 4; np++)
                ldm4(bq[np], qb + (u32)((np * 16 * LDT + ks * 16) * 2));
#pragma unroll
            for (int np = 0; np < 4; np++) {
                mma16816(S[2 * np], kA[ks], bq[np][0], bq[np][1]);
                mma16816(S[2 * np + 1], kA[ks], bq[np][2], bq[np][3]);
            }
        }
        // MMA2: ya[16j x 64d] += E[j][i] * vp[d][i]; E built per 16-i sub-chunk
        u32 vb = cur + 9216 + boff;
#pragma unroll
        for (int kc = 0; kc < 4; kc++) {
            u32 A2[4];
            A2[0] = pk_bf2(__expf(S[2 * kc][0]), __expf(S[2 * kc][1]));
            A2[1] = pk_bf2(__expf(S[2 * kc][2]), __expf(S[2 * kc][3]));
            A2[2] = pk_bf2(__expf(S[2 * kc + 1][0]), __expf(S[2 * kc + 1][1]));
            A2[3] = pk_bf2(__expf(S[2 * kc + 1][2]), __expf(S[2 * kc + 1][3]));
#pragma unroll
            for (int np = 0; np < 4; np++) {
                u32 bv[4];
                ldm4(bv, vb + (u32)((np * 16 * LDT + kc * 16) * 2));
                mma16816(ya[2 * np], A2, bv[0], bv[1]);
                mma16816(ya[2 * np + 1], A2, bv[2], bv[3]);
            }
        }
        __syncthreads();  // done reading cur; safe to overwrite
        if (ic + 2 < 64) {
            load_tile_async(cur, qsrc + (size_t)((ic + 2) * 64) * 192, 64, 192);
            load_tile_async(cur + 9216, vsrc + (ic + 2) * 64, 64, NTOK);
            cp_commit();
        }
    }

    // epilogue: direct bf16 write, disjoint per warp
    int j = j0 + wid * 16 + (l >> 2);
#pragma unroll
    for (int nt = 0; nt < 8; nt++) {
        int d = nt * 8 + (l & 3) * 2;
        *(u32*)(g_yT + ((size_t)b * NTOK + j) * 64 + d) = pk_bf2(ya[nt][0], ya[nt][1]);
        *(u32*)(g_yT + ((size_t)b * NTOK + j + 8) * 64 + d) = pk_bf2(ya[nt][2], ya[nt][3]);
    }
}

// ---------------- k_out ----------------
__global__ void __launch_bounds__(128) k_out(const float* __restrict__ x,
                                             const float* __restrict__ gamma,
                                             float* __restrict__ out) {
    bf16* At = (bf16*)dsm;            // yT tile 128x64 = 18432 B
    bf16* Bt = (bf16*)(dsm + 18432);  // Wo tile  64x64 =  9216 B
    float* Ts = (float*)dsm;          // reused: 64 x 132 f32 = 33792 B
    int j0 = blockIdx.x * 128, o0 = blockIdx.y * 64, b = blockIdx.z;
    int tid = threadIdx.x, wid = tid >> 5, l = tid & 31;
    load_tile(At, g_yT + ((size_t)b * NTOK + j0) * 64, 128, 64);
    load_tile(Bt, g_Wo + o0 * 64, 64, 64);
    __syncthreads();
    float acc[2][8][4];
#pragma unroll
    for (int mt = 0; mt < 2; mt++)
#pragma unroll
        for (int nt = 0; nt < 8; nt++)
#pragma unroll
            for (int e = 0; e < 4; e++) acc[mt][nt][e] = 0.f;
    wmma64<2, 4>(s2u(At) + (u32)(wid * 32 * LDT * 2), s2u(Bt), acc);
    __syncthreads();
#pragma unroll
    for (int mt = 0; mt < 2; mt++)
#pragma unroll
        for (int nt = 0; nt < 8; nt++) {
            int jl = wid * 32 + mt * 16 + (l >> 2);
            int ol = nt * 8 + (l & 3) * 2;
            Ts[ol * 132 + jl] = acc[mt][nt][0];
            Ts[(ol + 1) * 132 + jl] = acc[mt][nt][1];
            Ts[ol * 132 + jl + 8] = acc[mt][nt][2];
            Ts[(ol + 1) * 132 + jl + 8] = acc[mt][nt][3];
        }
    __syncthreads();
    float gm = gamma[0];
    int row = tid >> 1, half = (tid & 1) * 64;
    size_t goff = ((size_t)(b * 256 + o0 + row)) * NTOK + j0 + half;
#pragma unroll
    for (int q = 0; q < 16; q++) {
        float4 s = *(float4*)&Ts[row * 132 + half + q * 4];
        float4 xv = *(const float4*)&x[goff + q * 4];
        float4 o;
        o.x = fmaf(gm, s.x, xv.x);
        o.y = fmaf(gm, s.y, xv.y);
        o.z = fmaf(gm, s.z, xv.z);
        o.w = fmaf(gm, s.w, xv.w);
        *(float4*)&out[goff + q * 4] = o;
    }
}

extern "C" void kernel_launch(void* const* d_in, const int* in_sizes, int n_in,
                              void* d_out, int out_size) {
    const float* v = (const float*)d_in[0];
    const float* Wqkv = (const float*)d_in[1];
    const float* Wout = (const float*)d_in[2];
    const float* gamma = (const float*)d_in[3];
    float* out = (float*)d_out;

    k_prep<<<384, 256>>>(Wqkv, Wout);
    k_xT<<<dim3(64, 4, NB), 256>>>(v);
    k_qkv<<<dim3(32, NB), 256, 18432 + 27648>>>();
    k_lsum<<<dim3(32, NB), 256, 36864>>>();
    k_vp<<<dim3(64, NB), 256>>>();
    k_attn<<<dim3(32, NB), 256, 36864>>>();
    k_out<<<dim3(32, 4, NB), 128, 33792>>>(v, gamma, out);
}